// round 7
// baseline (speedup 1.0000x reference)
#include <cuda_runtime.h>
#include <cuda_bf16.h>
#include <math.h>

#define N_NODES 8000
#define N_EDGES 256000
#define F0      512

// ---------------- scratch (static device allocations; no cudaMalloc) --------
__device__ float g_w    [2][N_EDGES];
__device__ float g_dinv [2][N_NODES];
__device__ float g_coeff[2][N_EDGES];
__device__ int   g_hist [2][N_NODES];
__device__ int   g_offs [2][N_NODES + 1];
__device__ int   g_fill [2][N_NODES];
__device__ int   g_crow [2][N_EDGES];
__device__ float g_ccoef[2][N_EDGES];
__device__ float g_t    [2][N_NODES * F0];
__device__ __nv_bfloat16 g_tb[2][N_NODES * F0];   // bf16 copy of t for gather
__device__ float g_h    [2][N_NODES * F0];
__device__ float g_m1   [2][N_NODES * 256];
__device__ float g_m2   [2][N_NODES * 128];
__device__ float g_m3   [2][N_NODES * 64];

// ---------------- edge / degree prep (both graphs batched: blockIdx.y = g) --
__global__ void init_kernel() {
    int i = blockIdx.x * blockDim.x + threadIdx.x;
    int g = blockIdx.y;
    if (i < N_NODES) { g_dinv[g][i] = 1.0f; g_hist[g][i] = 0; }
}

__global__ void edge_kernel(const float* __restrict__ d0, const float* __restrict__ d1,
                            const int* __restrict__ e0, const int* __restrict__ e1) {
    int e = blockIdx.x * blockDim.x + threadIdx.x;
    int g = blockIdx.y;
    const float* data = g ? d1 : d0;
    const int*   ei   = g ? e1 : e0;
    if (e < N_EDGES) {
        int r = ei[e];
        int c = ei[N_EDGES + e];
        float v = fmaxf(data[(size_t)r * N_NODES + c], 0.0f);
        g_w[g][e] = v;
        atomicAdd(&g_dinv[g][c], v);
        atomicAdd(&g_hist[g][c], 1);
    }
}

__global__ void dinv_kernel() {
    int i = blockIdx.x * blockDim.x + threadIdx.x;
    int g = blockIdx.y;
    if (i < N_NODES) g_dinv[g][i] = rsqrtf(g_dinv[g][i]);
}

__global__ void coeff_kernel(const int* __restrict__ e0, const int* __restrict__ e1) {
    int e = blockIdx.x * blockDim.x + threadIdx.x;
    int g = blockIdx.y;
    const int* ei = g ? e1 : e0;
    if (e < N_EDGES) {
        int r = ei[e];
        int c = ei[N_EDGES + e];
        g_coeff[g][e] = g_dinv[g][r] * g_w[g][e] * g_dinv[g][c];
    }
}

__global__ void scan_kernel() {
    __shared__ int s[1024];
    int g = blockIdx.x;
    int t = threadIdx.x;
    int base = t * 8;
    int loc[8];
    int sum = 0;
#pragma unroll
    for (int j = 0; j < 8; j++) {
        int i = base + j;
        int v = (i < N_NODES) ? g_hist[g][i] : 0;
        loc[j] = sum;
        sum += v;
    }
    s[t] = sum;
    __syncthreads();
    for (int d = 1; d < 1024; d <<= 1) {
        int v = (t >= d) ? s[t - d] : 0;
        __syncthreads();
        s[t] += v;
        __syncthreads();
    }
    int cbase = s[t] - sum;
#pragma unroll
    for (int j = 0; j < 8; j++) {
        int i = base + j;
        if (i < N_NODES) {
            int o = cbase + loc[j];
            g_offs[g][i] = o;
            g_fill[g][i] = o;
        }
    }
    if (t == 0) g_offs[g][N_NODES] = N_EDGES;
}

__global__ void scatter_kernel(const int* __restrict__ e0, const int* __restrict__ e1) {
    int e = blockIdx.x * blockDim.x + threadIdx.x;
    int g = blockIdx.y;
    const int* ei = g ? e1 : e0;
    if (e < N_EDGES) {
        int c = ei[N_EDGES + e];
        int p = atomicAdd(&g_fill[g][c], 1);
        g_crow[g][p]  = ei[e];
        g_ccoef[g][p] = g_coeff[g][e];
    }
}

// ---------------- GCN aggregation (bf16 neighbor gather, fp32 self+accum) ----
__global__ void aggregate_kernel(const float* __restrict__ t0, const float* __restrict__ t1,
                                 const float* __restrict__ bias0, const float* __restrict__ bias1,
                                 float* __restrict__ o0, float* __restrict__ o1) {
    int c = blockIdx.x;
    int g = blockIdx.y;
    const float* t    = g ? t1 : t0;
    const float* bias = g ? bias1 : bias0;
    float* out        = g ? o1 : o0;
    const __nv_bfloat16* __restrict__ tb = g_tb[g];
    const int* __restrict__ crow = g_crow[g];
    const float* __restrict__ ccoef = g_ccoef[g];
    int f = threadIdx.x * 4;
    float dv = g_dinv[g][c];
    float sc = dv * dv;
    float4 v = *reinterpret_cast<const float4*>(&t[(size_t)c * F0 + f]);
    float4 acc = make_float4(v.x * sc, v.y * sc, v.z * sc, v.w * sc);
    int e0 = g_offs[g][c], e1 = g_offs[g][c + 1];
#pragma unroll 4
    for (int e = e0; e < e1; e++) {
        int   r  = crow[e];
        float cf = ccoef[e];
        uint2 raw = *reinterpret_cast<const uint2*>(&tb[(size_t)r * F0 + f]);
        float2 u0 = __bfloat1622float2(*reinterpret_cast<__nv_bfloat162*>(&raw.x));
        float2 u1 = __bfloat1622float2(*reinterpret_cast<__nv_bfloat162*>(&raw.y));
        acc.x += cf * u0.x; acc.y += cf * u0.y;
        acc.z += cf * u1.x; acc.w += cf * u1.y;
    }
    float4 b = *reinterpret_cast<const float4*>(&bias[f]);
    acc.x = fmaxf(acc.x + b.x, 0.0f);
    acc.y = fmaxf(acc.y + b.y, 0.0f);
    acc.z = fmaxf(acc.z + b.z, 0.0f);
    acc.w = fmaxf(acc.w + b.w, 0.0f);
    *reinterpret_cast<float4*>(&out[(size_t)c * F0 + f]) = acc;
}

// ---------------- TF32 tensor-core GEMM (128x128x16, 256 thr, reg prefetch) --
// C[Mn,Nn] = A[Mn,Kn] @ B  (B is [Kn,Nn] if !TRANSB else [Nn,Kn])
// WBF: additionally write bf16 copy of C into g_tb[blockIdx.z].
__device__ __forceinline__ unsigned f2tf(float x) {
    unsigned u;
    asm("cvt.rna.tf32.f32 %0, %1;" : "=r"(u) : "f"(x));
    return u;
}

template <bool TRANSB, bool BIAS, bool RELU, bool WBF>
__global__ __launch_bounds__(256)
void tf32_gemm(const float* __restrict__ A0, const float* __restrict__ A1,
               const float* __restrict__ B0, const float* __restrict__ B1,
               const float* __restrict__ bias0, const float* __restrict__ bias1,
               float* __restrict__ C0, float* __restrict__ C1,
               int Mn, int Nn, int Kn) {
    constexpr int BM = 128, BN = 128, BK = 16;
    constexpr int LDA = BK + 4;
    constexpr int LDB = BN + 4;
    __shared__ unsigned As[BM * LDA];
    __shared__ unsigned Bs[BK * LDB];

    const int gsel = blockIdx.z;
    const float* A    = gsel ? A1 : A0;
    const float* B    = gsel ? B1 : B0;
    const float* bias = gsel ? bias1 : bias0;
    float*       C    = gsel ? C1 : C0;
    __nv_bfloat16* CB = WBF ? g_tb[gsel] : nullptr;

    const int tid  = threadIdx.x;
    const int lane = tid & 31;
    const int wid  = tid >> 5;
    const int wm   = (wid & 1) * 64;
    const int wn   = (wid >> 1) * 32;
    const int q    = lane >> 2;
    const int r    = lane & 3;
    const int m0   = blockIdx.y * BM;
    const int n0   = blockIdx.x * BN;

    float c[4][4][4];
#pragma unroll
    for (int i = 0; i < 4; i++)
#pragma unroll
        for (int j = 0; j < 4; j++)
#pragma unroll
            for (int k = 0; k < 4; k++) c[i][j][k] = 0.0f;

    float4 ra[2], rb[2];

    auto loadA = [&](int k0) {
#pragma unroll
        for (int i = 0; i < 2; i++) {
            int l = tid + i * 256;
            int row = l >> 2;
            int kq  = (l & 3) * 4;
            float4 v = make_float4(0.f, 0.f, 0.f, 0.f);
            if (m0 + row < Mn)
                v = *reinterpret_cast<const float4*>(&A[(size_t)(m0 + row) * Kn + k0 + kq]);
            ra[i] = v;
        }
    };
    auto loadB = [&](int k0) {
#pragma unroll
        for (int i = 0; i < 2; i++) {
            int l = tid + i * 256;
            float4 v = make_float4(0.f, 0.f, 0.f, 0.f);
            if (!TRANSB) {
                int k  = l >> 5;
                int nq = (l & 31) * 4;
                if (n0 + nq < Nn)
                    v = *reinterpret_cast<const float4*>(&B[(size_t)(k0 + k) * Nn + n0 + nq]);
            } else {
                int n  = l >> 2;
                int kq = (l & 3) * 4;
                if (n0 + n < Nn)
                    v = *reinterpret_cast<const float4*>(&B[(size_t)(n0 + n) * Kn + k0 + kq]);
            }
            rb[i] = v;
        }
    };
    auto storeA = [&]() {
#pragma unroll
        for (int i = 0; i < 2; i++) {
            int l = tid + i * 256;
            int row = l >> 2;
            int kq  = (l & 3) * 4;
            As[row * LDA + kq + 0] = f2tf(ra[i].x);
            As[row * LDA + kq + 1] = f2tf(ra[i].y);
            As[row * LDA + kq + 2] = f2tf(ra[i].z);
            As[row * LDA + kq + 3] = f2tf(ra[i].w);
        }
    };
    auto storeB = [&]() {
#pragma unroll
        for (int i = 0; i < 2; i++) {
            int l = tid + i * 256;
            if (!TRANSB) {
                int k  = l >> 5;
                int nq = (l & 31) * 4;
                Bs[k * LDB + nq + 0] = f2tf(rb[i].x);
                Bs[k * LDB + nq + 1] = f2tf(rb[i].y);
                Bs[k * LDB + nq + 2] = f2tf(rb[i].z);
                Bs[k * LDB + nq + 3] = f2tf(rb[i].w);
            } else {
                int n  = l >> 2;
                int kq = (l & 3) * 4;
                Bs[(kq + 0) * LDB + n] = f2tf(rb[i].x);
                Bs[(kq + 1) * LDB + n] = f2tf(rb[i].y);
                Bs[(kq + 2) * LDB + n] = f2tf(rb[i].z);
                Bs[(kq + 3) * LDB + n] = f2tf(rb[i].w);
            }
        }
    };

    loadA(0);
    loadB(0);

    for (int k0 = 0; k0 < Kn; k0 += BK) {
        storeA();
        storeB();
        __syncthreads();
        if (k0 + BK < Kn) { loadA(k0 + BK); loadB(k0 + BK); }

#pragma unroll
        for (int kk = 0; kk < BK; kk += 8) {
            unsigned a[4][4], b[4][2];
#pragma unroll
            for (int tm = 0; tm < 4; tm++) {
                int row = wm + tm * 16 + q;
                a[tm][0] = As[(row)     * LDA + kk + r];
                a[tm][1] = As[(row + 8) * LDA + kk + r];
                a[tm][2] = As[(row)     * LDA + kk + 4 + r];
                a[tm][3] = As[(row + 8) * LDA + kk + 4 + r];
            }
#pragma unroll
            for (int tn = 0; tn < 4; tn++) {
                int col = wn + tn * 8 + q;
                b[tn][0] = Bs[(kk + r)     * LDB + col];
                b[tn][1] = Bs[(kk + 4 + r) * LDB + col];
            }
#pragma unroll
            for (int tm = 0; tm < 4; tm++)
#pragma unroll
                for (int tn = 0; tn < 4; tn++) {
                    asm volatile(
                        "mma.sync.aligned.m16n8k8.row.col.f32.tf32.tf32.f32 "
                        "{%0,%1,%2,%3}, {%4,%5,%6,%7}, {%8,%9}, {%0,%1,%2,%3};"
                        : "+f"(c[tm][tn][0]), "+f"(c[tm][tn][1]),
                          "+f"(c[tm][tn][2]), "+f"(c[tm][tn][3])
                        : "r"(a[tm][0]), "r"(a[tm][1]), "r"(a[tm][2]), "r"(a[tm][3]),
                          "r"(b[tn][0]), "r"(b[tn][1]));
                }
        }
        __syncthreads();
    }

#pragma unroll
    for (int tm = 0; tm < 4; tm++) {
        int row = m0 + wm + tm * 16 + q;
#pragma unroll
        for (int tn = 0; tn < 4; tn++) {
            int col = n0 + wn + tn * 8 + 2 * r;
            if (col >= Nn) continue;
            float v0 = c[tm][tn][0], v1 = c[tm][tn][1];
            float v2 = c[tm][tn][2], v3 = c[tm][tn][3];
            if (BIAS) {
                float bb0 = bias[col], bb1 = bias[col + 1];
                v0 += bb0; v1 += bb1; v2 += bb0; v3 += bb1;
            }
            if (RELU) {
                v0 = fmaxf(v0, 0.f); v1 = fmaxf(v1, 0.f);
                v2 = fmaxf(v2, 0.f); v3 = fmaxf(v3, 0.f);
            }
            if (row < Mn) {
                *reinterpret_cast<float2*>(&C[(size_t)row * Nn + col]) = make_float2(v0, v1);
                if (WBF)
                    *reinterpret_cast<__nv_bfloat162*>(&CB[(size_t)row * Nn + col]) =
                        __floats2bfloat162_rn(v0, v1);
            }
            if (row + 8 < Mn) {
                *reinterpret_cast<float2*>(&C[(size_t)(row + 8) * Nn + col]) = make_float2(v2, v3);
                if (WBF)
                    *reinterpret_cast<__nv_bfloat162*>(&CB[(size_t)(row + 8) * Nn + col]) =
                        __floats2bfloat162_rn(v2, v3);
            }
        }
    }
}

// ---------------- fp32 GEMM for narrow MLP layers (blockIdx.z = g) -----------
template <int BM, int BN, int BK, int TM, int TN, bool BIAS, bool RELU>
__global__ __launch_bounds__((BM / TM) * (BN / TN))
void gemm_kernel(const float* __restrict__ A0, const float* __restrict__ A1,
                 const float* __restrict__ B0, const float* __restrict__ B1,
                 const float* __restrict__ bias0, const float* __restrict__ bias1,
                 float* __restrict__ C0, float* __restrict__ C1,
                 int Mn, int Nn, int Kn) {
    constexpr int THREADS = (BM / TM) * (BN / TN);
    __shared__ float As[BK][BM];
    __shared__ float Bs[BK][BN];
    const int gsel = blockIdx.z;
    const float* A    = gsel ? A1 : A0;
    const float* B    = gsel ? B1 : B0;
    const float* bias = gsel ? bias1 : bias0;
    float*       C    = gsel ? C1 : C0;
    const int tid = threadIdx.x;
    const int tx = tid % (BN / TN);
    const int ty = tid / (BN / TN);
    const int m0 = blockIdx.y * BM;
    const int n0 = blockIdx.x * BN;

    float acc[TM][TN];
#pragma unroll
    for (int i = 0; i < TM; i++)
#pragma unroll
        for (int j = 0; j < TN; j++) acc[i][j] = 0.0f;

    for (int k0 = 0; k0 < Kn; k0 += BK) {
#pragma unroll
        for (int l = tid; l < BM * BK / 4; l += THREADS) {
            int row = l / (BK / 4);
            int kq  = (l % (BK / 4)) * 4;
            float4 v = make_float4(0.f, 0.f, 0.f, 0.f);
            if (m0 + row < Mn)
                v = *reinterpret_cast<const float4*>(&A[(size_t)(m0 + row) * Kn + k0 + kq]);
            As[kq + 0][row] = v.x; As[kq + 1][row] = v.y;
            As[kq + 2][row] = v.z; As[kq + 3][row] = v.w;
        }
#pragma unroll
        for (int l = tid; l < BK * BN / 4; l += THREADS) {
            int kk = l / (BN / 4);
            int nq = (l % (BN / 4)) * 4;
            float4 v = make_float4(0.f, 0.f, 0.f, 0.f);
            if (n0 + nq < Nn)
                v = *reinterpret_cast<const float4*>(&B[(size_t)(k0 + kk) * Nn + n0 + nq]);
            *reinterpret_cast<float4*>(&Bs[kk][nq]) = v;
        }
        __syncthreads();
#pragma unroll
        for (int k = 0; k < BK; k++) {
            float a[TM], b[TN];
#pragma unroll
            for (int i = 0; i < TM; i++) a[i] = As[k][ty * TM + i];
#pragma unroll
            for (int j = 0; j < TN; j++) b[j] = Bs[k][tx * TN + j];
#pragma unroll
            for (int i = 0; i < TM; i++)
#pragma unroll
                for (int j = 0; j < TN; j++) acc[i][j] += a[i] * b[j];
        }
        __syncthreads();
    }
#pragma unroll
    for (int i = 0; i < TM; i++) {
        int m = m0 + ty * TM + i;
        if (m >= Mn) continue;
#pragma unroll
        for (int j = 0; j < TN; j += 4) {
            int n = n0 + tx * TN + j;
            if (n >= Nn) continue;
            float4 v = make_float4(acc[i][j], acc[i][j + 1], acc[i][j + 2], acc[i][j + 3]);
            if (BIAS) {
                v.x += bias[n]; v.y += bias[n + 1]; v.z += bias[n + 2]; v.w += bias[n + 3];
            }
            if (RELU) {
                v.x = fmaxf(v.x, 0.f); v.y = fmaxf(v.y, 0.f);
                v.z = fmaxf(v.z, 0.f); v.w = fmaxf(v.w, 0.f);
            }
            *reinterpret_cast<float4*>(&C[(size_t)m * Nn + n]) = v;
        }
    }
}

// ---------------- host-side orchestration -----------------------------------
extern "C" void kernel_launch(void* const* d_in, const int* in_sizes, int n_in,
                              void* d_out, int out_size) {
    const float* x_in[2]  = { (const float*)d_in[0], (const float*)d_in[1] };
    const float* dmat[2]  = { (const float*)d_in[2], (const float*)d_in[3] };
    const int*   ei[2]    = { (const int*)d_in[4],   (const int*)d_in[5]   };
    const float* W1[2]    = { (const float*)d_in[6],  (const float*)d_in[10] };
    const float* b1[2]    = { (const float*)d_in[7],  (const float*)d_in[11] };
    const float* W2[2]    = { (const float*)d_in[8],  (const float*)d_in[12] };
    const float* b2[2]    = { (const float*)d_in[9],  (const float*)d_in[13] };
    const float* L1w[2]   = { (const float*)d_in[14], (const float*)d_in[20] };
    const float* L1b[2]   = { (const float*)d_in[15], (const float*)d_in[21] };
    const float* L2w[2]   = { (const float*)d_in[16], (const float*)d_in[22] };
    const float* L2b[2]   = { (const float*)d_in[17], (const float*)d_in[23] };
    const float* L3w[2]   = { (const float*)d_in[18], (const float*)d_in[24] };
    const float* L3b[2]   = { (const float*)d_in[19], (const float*)d_in[25] };
    float* out = (float*)d_out;

    float *p_t, *p_h, *p_m1, *p_m2, *p_m3;
    cudaGetSymbolAddress((void**)&p_t,  g_t);
    cudaGetSymbolAddress((void**)&p_h,  g_h);
    cudaGetSymbolAddress((void**)&p_m1, g_m1);
    cudaGetSymbolAddress((void**)&p_m2, g_m2);
    cudaGetSymbolAddress((void**)&p_m3, g_m3);

    float* t[2]  = { p_t,  p_t  + (size_t)N_NODES * F0 };
    float* h[2]  = { p_h,  p_h  + (size_t)N_NODES * F0 };
    float* m1[2] = { p_m1, p_m1 + (size_t)N_NODES * 256 };
    float* m2[2] = { p_m2, p_m2 + (size_t)N_NODES * 128 };
    float* m3[2] = { p_m3, p_m3 + (size_t)N_NODES * 64 };

    const int TB = 256;
    const dim3 gN((N_NODES + TB - 1) / TB, 2);
    const dim3 gE((N_EDGES + TB - 1) / TB, 2);
    const int MB = (N_NODES + 127) / 128;   // 63

    init_kernel<<<gN, TB>>>();
    edge_kernel<<<gE, TB>>>(dmat[0], dmat[1], ei[0], ei[1]);
    dinv_kernel<<<gN, TB>>>();
    coeff_kernel<<<gE, TB>>>(ei[0], ei[1]);
    scan_kernel<<<2, 1024>>>();
    scatter_kernel<<<gE, TB>>>(ei[0], ei[1]);

    // GCN layer 1: t = x @ W1 (fp32 + bf16 copy) ; h = relu(agg(t) + b1)
    tf32_gemm<false, false, false, true><<<dim3(F0 / 128, MB, 2), 256>>>(
        x_in[0], x_in[1], W1[0], W1[1], nullptr, nullptr, t[0], t[1],
        N_NODES, F0, F0);
    aggregate_kernel<<<dim3(N_NODES, 2), 128>>>(t[0], t[1], b1[0], b1[1], h[0], h[1]);

    // GCN layer 2
    tf32_gemm<false, false, false, true><<<dim3(F0 / 128, MB, 2), 256>>>(
        h[0], h[1], W2[0], W2[1], nullptr, nullptr, t[0], t[1],
        N_NODES, F0, F0);
    aggregate_kernel<<<dim3(N_NODES, 2), 128>>>(t[0], t[1], b2[0], b2[1], h[0], h[1]);

    // MLP: L1 tf32 (512->256), L2/L3 fp32
    tf32_gemm<false, true, true, false><<<dim3(256 / 128, MB, 2), 256>>>(
        h[0], h[1], L1w[0], L1w[1], L1b[0], L1b[1], m1[0], m1[1],
        N_NODES, 256, F0);
    gemm_kernel<64, 64, 16, 4, 4, true, true>
        <<<dim3(2, (N_NODES + 63) / 64, 2), 256>>>(
            m1[0], m1[1], L2w[0], L2w[1], L2b[0], L2b[1], m2[0], m2[1],
            N_NODES, 128, 256);
    gemm_kernel<64, 64, 16, 4, 4, true, true>
        <<<dim3(1, (N_NODES + 63) / 64, 2), 256>>>(
            m2[0], m2[1], L3w[0], L3w[1], L3b[0], L3b[1], m3[0], m3[1],
            N_NODES, 64, 128);

    // final (tf32, TRANSB): out = x64_m @ y64_d^T  [8000 x 8000]
    tf32_gemm<true, false, false, false><<<dim3((N_NODES + 127) / 128, MB, 1), 256>>>(
        m3[0], m3[0], m3[1], m3[1], nullptr, nullptr, out, out,
        N_NODES, N_NODES, 64);
}

// round 8
// speedup vs baseline: 1.2641x; 1.2641x over previous
#include <cuda_runtime.h>
#include <cuda_fp16.h>
#include <math.h>

#define N_NODES 8000
#define N_EDGES 256000
#define F0      512

// ---------------- scratch (static device allocations; no cudaMalloc) --------
__device__ float g_w    [2][N_EDGES];
__device__ float g_dinv [2][N_NODES];
__device__ float g_coeff[2][N_EDGES];
__device__ int   g_hist [2][N_NODES];
__device__ int   g_offs [2][N_NODES + 1];
__device__ int   g_fill [2][N_NODES];
__device__ int   g_crow [2][N_EDGES];
__device__ float g_ccoef[2][N_EDGES];
__device__ float g_t    [2][N_NODES * F0];
__device__ float g_h    [2][N_NODES * F0];
__device__ float g_m1   [2][N_NODES * 256];
__device__ float g_m2   [2][N_NODES * 128];
__device__ float g_m3   [2][N_NODES * 64];

// ---------------- edge / degree prep (both graphs batched: blockIdx.y = g) --
__global__ void init_kernel() {
    int i = blockIdx.x * blockDim.x + threadIdx.x;
    int g = blockIdx.y;
    if (i < N_NODES) { g_dinv[g][i] = 1.0f; g_hist[g][i] = 0; }
}

__global__ void edge_kernel(const float* __restrict__ d0, const float* __restrict__ d1,
                            const int* __restrict__ e0, const int* __restrict__ e1) {
    int e = blockIdx.x * blockDim.x + threadIdx.x;
    int g = blockIdx.y;
    const float* data = g ? d1 : d0;
    const int*   ei   = g ? e1 : e0;
    if (e < N_EDGES) {
        int r = ei[e];
        int c = ei[N_EDGES + e];
        float v = fmaxf(data[(size_t)r * N_NODES + c], 0.0f);
        g_w[g][e] = v;
        atomicAdd(&g_dinv[g][c], v);
        atomicAdd(&g_hist[g][c], 1);
    }
}

__global__ void dinv_kernel() {
    int i = blockIdx.x * blockDim.x + threadIdx.x;
    int g = blockIdx.y;
    if (i < N_NODES) g_dinv[g][i] = rsqrtf(g_dinv[g][i]);
}

__global__ void coeff_kernel(const int* __restrict__ e0, const int* __restrict__ e1) {
    int e = blockIdx.x * blockDim.x + threadIdx.x;
    int g = blockIdx.y;
    const int* ei = g ? e1 : e0;
    if (e < N_EDGES) {
        int r = ei[e];
        int c = ei[N_EDGES + e];
        g_coeff[g][e] = g_dinv[g][r] * g_w[g][e] * g_dinv[g][c];
    }
}

__global__ void scan_kernel() {
    __shared__ int s[1024];
    int g = blockIdx.x;
    int t = threadIdx.x;
    int base = t * 8;
    int loc[8];
    int sum = 0;
#pragma unroll
    for (int j = 0; j < 8; j++) {
        int i = base + j;
        int v = (i < N_NODES) ? g_hist[g][i] : 0;
        loc[j] = sum;
        sum += v;
    }
    s[t] = sum;
    __syncthreads();
    for (int d = 1; d < 1024; d <<= 1) {
        int v = (t >= d) ? s[t - d] : 0;
        __syncthreads();
        s[t] += v;
        __syncthreads();
    }
    int cbase = s[t] - sum;
#pragma unroll
    for (int j = 0; j < 8; j++) {
        int i = base + j;
        if (i < N_NODES) {
            int o = cbase + loc[j];
            g_offs[g][i] = o;
            g_fill[g][i] = o;
        }
    }
    if (t == 0) g_offs[g][N_NODES] = N_EDGES;
}

__global__ void scatter_kernel(const int* __restrict__ e0, const int* __restrict__ e1) {
    int e = blockIdx.x * blockDim.x + threadIdx.x;
    int g = blockIdx.y;
    const int* ei = g ? e1 : e0;
    if (e < N_EDGES) {
        int c = ei[N_EDGES + e];
        int p = atomicAdd(&g_fill[g][c], 1);
        g_crow[g][p]  = ei[e];
        g_ccoef[g][p] = g_coeff[g][e];
    }
}

// ---------------- GCN aggregation (fp32 gather, fp32 accum) ------------------
__global__ void aggregate_kernel(const float* __restrict__ t0, const float* __restrict__ t1,
                                 const float* __restrict__ bias0, const float* __restrict__ bias1,
                                 float* __restrict__ o0, float* __restrict__ o1) {
    int c = blockIdx.x;
    int g = blockIdx.y;
    const float* t    = g ? t1 : t0;
    const float* bias = g ? bias1 : bias0;
    float* out        = g ? o1 : o0;
    const int* __restrict__ crow = g_crow[g];
    const float* __restrict__ ccoef = g_ccoef[g];
    int f = threadIdx.x * 4;
    float dv = g_dinv[g][c];
    float sc = dv * dv;
    float4 v = *reinterpret_cast<const float4*>(&t[(size_t)c * F0 + f]);
    float4 acc = make_float4(v.x * sc, v.y * sc, v.z * sc, v.w * sc);
    int e0 = g_offs[g][c], e1 = g_offs[g][c + 1];
#pragma unroll 4
    for (int e = e0; e < e1; e++) {
        int   r  = crow[e];
        float cf = ccoef[e];
        float4 u = *reinterpret_cast<const float4*>(&t[(size_t)r * F0 + f]);
        acc.x += cf * u.x; acc.y += cf * u.y; acc.z += cf * u.z; acc.w += cf * u.w;
    }
    float4 b = *reinterpret_cast<const float4*>(&bias[f]);
    acc.x = fmaxf(acc.x + b.x, 0.0f);
    acc.y = fmaxf(acc.y + b.y, 0.0f);
    acc.z = fmaxf(acc.z + b.z, 0.0f);
    acc.w = fmaxf(acc.w + b.w, 0.0f);
    *reinterpret_cast<float4*>(&out[(size_t)c * F0 + f]) = acc;
}

// ---------------- FP16 tensor-core GEMM (128x128x32, 256 thr, reg prefetch) --
// C[Mn,Nn] = A[Mn,Kn] @ B  (B is [Kn,Nn] if !TRANSB else [Nn,Kn])
// fp16 inputs (10-bit mantissa == tf32), fp32 accumulate. Kn % 32 == 0.
__device__ __forceinline__ unsigned packh2(float a, float b) {
    __half2 h = __floats2half2_rn(a, b);
    return *reinterpret_cast<unsigned*>(&h);
}

template <bool TRANSB, bool BIAS, bool RELU>
__global__ __launch_bounds__(256)
void fp16_gemm(const float* __restrict__ A0, const float* __restrict__ A1,
               const float* __restrict__ B0, const float* __restrict__ B1,
               const float* __restrict__ bias0, const float* __restrict__ bias1,
               float* __restrict__ C0, float* __restrict__ C1,
               int Mn, int Nn, int Kn) {
    constexpr int BM = 128, BN = 128, BK = 32;
    constexpr int LDA = BK / 2 + 4;   // 20 words/row: fragment loads conflict-free
    constexpr int LDB = BN + 8;       // 136 words/row: fragment loads conflict-free
    __shared__ unsigned As[BM * LDA];           // half2 words, [m][kpair]
    __shared__ unsigned Bs[(BK / 2) * LDB];     // half2 words, [kpair][n]

    const int gsel = blockIdx.z;
    const float* A    = gsel ? A1 : A0;
    const float* B    = gsel ? B1 : B0;
    const float* bias = gsel ? bias1 : bias0;
    float*       C    = gsel ? C1 : C0;

    const int tid  = threadIdx.x;
    const int lane = tid & 31;
    const int wid  = tid >> 5;
    const int wm   = (wid & 1) * 64;
    const int wn   = (wid >> 1) * 32;
    const int q    = lane >> 2;
    const int r    = lane & 3;
    const int m0   = blockIdx.y * BM;
    const int n0   = blockIdx.x * BN;

    float c[4][4][4];
#pragma unroll
    for (int i = 0; i < 4; i++)
#pragma unroll
        for (int j = 0; j < 4; j++)
#pragma unroll
            for (int k = 0; k < 4; k++) c[i][j][k] = 0.0f;

    float4 ra[4], rb[4];

    // ---- A tile: 128 rows x 32 floats = 1024 float4, 4 per thread ----
    auto loadA = [&](int k0) {
#pragma unroll
        for (int i = 0; i < 4; i++) {
            int l = tid + i * 256;
            int row = l >> 3;
            int fq  = l & 7;
            float4 v = make_float4(0.f, 0.f, 0.f, 0.f);
            if (m0 + row < Mn)
                v = *reinterpret_cast<const float4*>(&A[(size_t)(m0 + row) * Kn + k0 + 4 * fq]);
            ra[i] = v;
        }
    };
    auto storeA = [&]() {
#pragma unroll
        for (int i = 0; i < 4; i++) {
            int l = tid + i * 256;
            int row = l >> 3;
            int fq  = l & 7;
            As[row * LDA + 2 * fq + 0] = packh2(ra[i].x, ra[i].y);
            As[row * LDA + 2 * fq + 1] = packh2(ra[i].z, ra[i].w);
        }
    };
    // ---- B tile ----
    auto loadB = [&](int k0) {
        if (!TRANSB) {
            // pairs of K rows: 512 pair-tasks, 2 per thread, each loads 2 float4
#pragma unroll
            for (int i = 0; i < 2; i++) {
                int p  = tid + i * 256;
                int kp = p >> 5;             // 0..15
                int nq = (p & 31) << 2;      // 0..124
                float4 lo = make_float4(0.f, 0.f, 0.f, 0.f);
                float4 hi = make_float4(0.f, 0.f, 0.f, 0.f);
                if (n0 + nq < Nn) {
                    lo = *reinterpret_cast<const float4*>(&B[(size_t)(k0 + 2 * kp)     * Nn + n0 + nq]);
                    hi = *reinterpret_cast<const float4*>(&B[(size_t)(k0 + 2 * kp + 1) * Nn + n0 + nq]);
                }
                rb[2 * i + 0] = lo;
                rb[2 * i + 1] = hi;
            }
        } else {
            // [Nn][Kn] rows: 128 n-rows x 8 float4 = 1024, 4 per thread
#pragma unroll
            for (int i = 0; i < 4; i++) {
                int l = tid + i * 256;
                int n  = l >> 3;
                int fq = l & 7;
                float4 v = make_float4(0.f, 0.f, 0.f, 0.f);
                if (n0 + n < Nn)
                    v = *reinterpret_cast<const float4*>(&B[(size_t)(n0 + n) * Kn + k0 + 4 * fq]);
                rb[i] = v;
            }
        }
    };
    auto storeB = [&]() {
        if (!TRANSB) {
#pragma unroll
            for (int i = 0; i < 2; i++) {
                int p  = tid + i * 256;
                int kp = p >> 5;
                int nq = (p & 31) << 2;
                float4 lo = rb[2 * i + 0];
                float4 hi = rb[2 * i + 1];
                Bs[kp * LDB + nq + 0] = packh2(lo.x, hi.x);
                Bs[kp * LDB + nq + 1] = packh2(lo.y, hi.y);
                Bs[kp * LDB + nq + 2] = packh2(lo.z, hi.z);
                Bs[kp * LDB + nq + 3] = packh2(lo.w, hi.w);
            }
        } else {
#pragma unroll
            for (int i = 0; i < 4; i++) {
                int l = tid + i * 256;
                int n  = l >> 3;
                int fq = l & 7;
                float4 v = rb[i];
                Bs[(2 * fq + 0) * LDB + n] = packh2(v.x, v.y);
                Bs[(2 * fq + 1) * LDB + n] = packh2(v.z, v.w);
            }
        }
    };

    loadA(0);
    loadB(0);

    for (int k0 = 0; k0 < Kn; k0 += BK) {
        storeA();
        storeB();
        __syncthreads();
        if (k0 + BK < Kn) { loadA(k0 + BK); loadB(k0 + BK); }

#pragma unroll
        for (int ks = 0; ks < BK / 2; ks += 8) {   // two m16n8k16 K-steps per tile
            unsigned a[4][4], b[4][2];
#pragma unroll
            for (int tm = 0; tm < 4; tm++) {
                int row = wm + tm * 16 + q;
                a[tm][0] = As[(row)     * LDA + ks + r];
                a[tm][1] = As[(row + 8) * LDA + ks + r];
                a[tm][2] = As[(row)     * LDA + ks + 4 + r];
                a[tm][3] = As[(row + 8) * LDA + ks + 4 + r];
            }
#pragma unroll
            for (int tn = 0; tn < 4; tn++) {
                int col = wn + tn * 8 + q;
                b[tn][0] = Bs[(ks + r)     * LDB + col];
                b[tn][1] = Bs[(ks + 4 + r) * LDB + col];
            }
#pragma unroll
            for (int tm = 0; tm < 4; tm++)
#pragma unroll
                for (int tn = 0; tn < 4; tn++) {
                    asm volatile(
                        "mma.sync.aligned.m16n8k16.row.col.f32.f16.f16.f32 "
                        "{%0,%1,%2,%3}, {%4,%5,%6,%7}, {%8,%9}, {%0,%1,%2,%3};"
                        : "+f"(c[tm][tn][0]), "+f"(c[tm][tn][1]),
                          "+f"(c[tm][tn][2]), "+f"(c[tm][tn][3])
                        : "r"(a[tm][0]), "r"(a[tm][1]), "r"(a[tm][2]), "r"(a[tm][3]),
                          "r"(b[tn][0]), "r"(b[tn][1]));
                }
        }
        __syncthreads();
    }

    // epilogue
#pragma unroll
    for (int tm = 0; tm < 4; tm++) {
        int row = m0 + wm + tm * 16 + q;
#pragma unroll
        for (int tn = 0; tn < 4; tn++) {
            int col = n0 + wn + tn * 8 + 2 * r;
            if (col >= Nn) continue;
            float v0 = c[tm][tn][0], v1 = c[tm][tn][1];
            float v2 = c[tm][tn][2], v3 = c[tm][tn][3];
            if (BIAS) {
                float bb0 = bias[col], bb1 = bias[col + 1];
                v0 += bb0; v1 += bb1; v2 += bb0; v3 += bb1;
            }
            if (RELU) {
                v0 = fmaxf(v0, 0.f); v1 = fmaxf(v1, 0.f);
                v2 = fmaxf(v2, 0.f); v3 = fmaxf(v3, 0.f);
            }
            if (row < Mn)
                *reinterpret_cast<float2*>(&C[(size_t)row * Nn + col]) = make_float2(v0, v1);
            if (row + 8 < Mn)
                *reinterpret_cast<float2*>(&C[(size_t)(row + 8) * Nn + col]) = make_float2(v2, v3);
        }
    }
}

// ---------------- fp32 GEMM for narrow MLP layers (blockIdx.z = g) -----------
template <int BM, int BN, int BK, int TM, int TN, bool BIAS, bool RELU>
__global__ __launch_bounds__((BM / TM) * (BN / TN))
void gemm_kernel(const float* __restrict__ A0, const float* __restrict__ A1,
                 const float* __restrict__ B0, const float* __restrict__ B1,
                 const float* __restrict__ bias0, const float* __restrict__ bias1,
                 float* __restrict__ C0, float* __restrict__ C1,
                 int Mn, int Nn, int Kn) {
    constexpr int THREADS = (BM / TM) * (BN / TN);
    __shared__ float As[BK][BM];
    __shared__ float Bs[BK][BN];
    const int gsel = blockIdx.z;
    const float* A    = gsel ? A1 : A0;
    const float* B    = gsel ? B1 : B0;
    const float* bias = gsel ? bias1 : bias0;
    float*       C    = gsel ? C1 : C0;
    const int tid = threadIdx.x;
    const int tx = tid % (BN / TN);
    const int ty = tid / (BN / TN);
    const int m0 = blockIdx.y * BM;
    const int n0 = blockIdx.x * BN;

    float acc[TM][TN];
#pragma unroll
    for (int i = 0; i < TM; i++)
#pragma unroll
        for (int j = 0; j < TN; j++) acc[i][j] = 0.0f;

    for (int k0 = 0; k0 < Kn; k0 += BK) {
#pragma unroll
        for (int l = tid; l < BM * BK / 4; l += THREADS) {
            int row = l / (BK / 4);
            int kq  = (l % (BK / 4)) * 4;
            float4 v = make_float4(0.f, 0.f, 0.f, 0.f);
            if (m0 + row < Mn)
                v = *reinterpret_cast<const float4*>(&A[(size_t)(m0 + row) * Kn + k0 + kq]);
            As[kq + 0][row] = v.x; As[kq + 1][row] = v.y;
            As[kq + 2][row] = v.z; As[kq + 3][row] = v.w;
        }
#pragma unroll
        for (int l = tid; l < BK * BN / 4; l += THREADS) {
            int kk = l / (BN / 4);
            int nq = (l % (BN / 4)) * 4;
            float4 v = make_float4(0.f, 0.f, 0.f, 0.f);
            if (n0 + nq < Nn)
                v = *reinterpret_cast<const float4*>(&B[(size_t)(k0 + kk) * Nn + n0 + nq]);
            *reinterpret_cast<float4*>(&Bs[kk][nq]) = v;
        }
        __syncthreads();
#pragma unroll
        for (int k = 0; k < BK; k++) {
            float a[TM], b[TN];
#pragma unroll
            for (int i = 0; i < TM; i++) a[i] = As[k][ty * TM + i];
#pragma unroll
            for (int j = 0; j < TN; j++) b[j] = Bs[k][tx * TN + j];
#pragma unroll
            for (int i = 0; i < TM; i++)
#pragma unroll
                for (int j = 0; j < TN; j++) acc[i][j] += a[i] * b[j];
        }
        __syncthreads();
    }
#pragma unroll
    for (int i = 0; i < TM; i++) {
        int m = m0 + ty * TM + i;
        if (m >= Mn) continue;
#pragma unroll
        for (int j = 0; j < TN; j += 4) {
            int n = n0 + tx * TN + j;
            if (n >= Nn) continue;
            float4 v = make_float4(acc[i][j], acc[i][j + 1], acc[i][j + 2], acc[i][j + 3]);
            if (BIAS) {
                v.x += bias[n]; v.y += bias[n + 1]; v.z += bias[n + 2]; v.w += bias[n + 3];
            }
            if (RELU) {
                v.x = fmaxf(v.x, 0.f); v.y = fmaxf(v.y, 0.f);
                v.z = fmaxf(v.z, 0.f); v.w = fmaxf(v.w, 0.f);
            }
            *reinterpret_cast<float4*>(&C[(size_t)m * Nn + n]) = v;
        }
    }
}

// ---------------- host-side orchestration -----------------------------------
extern "C" void kernel_launch(void* const* d_in, const int* in_sizes, int n_in,
                              void* d_out, int out_size) {
    const float* x_in[2]  = { (const float*)d_in[0], (const float*)d_in[1] };
    const float* dmat[2]  = { (const float*)d_in[2], (const float*)d_in[3] };
    const int*   ei[2]    = { (const int*)d_in[4],   (const int*)d_in[5]   };
    const float* W1[2]    = { (const float*)d_in[6],  (const float*)d_in[10] };
    const float* b1[2]    = { (const float*)d_in[7],  (const float*)d_in[11] };
    const float* W2[2]    = { (const float*)d_in[8],  (const float*)d_in[12] };
    const float* b2[2]    = { (const float*)d_in[9],  (const float*)d_in[13] };
    const float* L1w[2]   = { (const float*)d_in[14], (const float*)d_in[20] };
    const float* L1b[2]   = { (const float*)d_in[15], (const float*)d_in[21] };
    const float* L2w[2]   = { (const float*)d_in[16], (const float*)d_in[22] };
    const float* L2b[2]   = { (const float*)d_in[17], (const float*)d_in[23] };
    const float* L3w[2]   = { (const float*)d_in[18], (const float*)d_in[24] };
    const float* L3b[2]   = { (const float*)d_in[19], (const float*)d_in[25] };
    float* out = (float*)d_out;

    float *p_t, *p_h, *p_m1, *p_m2, *p_m3;
    cudaGetSymbolAddress((void**)&p_t,  g_t);
    cudaGetSymbolAddress((void**)&p_h,  g_h);
    cudaGetSymbolAddress((void**)&p_m1, g_m1);
    cudaGetSymbolAddress((void**)&p_m2, g_m2);
    cudaGetSymbolAddress((void**)&p_m3, g_m3);

    float* t[2]  = { p_t,  p_t  + (size_t)N_NODES * F0 };
    float* h[2]  = { p_h,  p_h  + (size_t)N_NODES * F0 };
    float* m1[2] = { p_m1, p_m1 + (size_t)N_NODES * 256 };
    float* m2[2] = { p_m2, p_m2 + (size_t)N_NODES * 128 };
    float* m3[2] = { p_m3, p_m3 + (size_t)N_NODES * 64 };

    const int TB = 256;
    const dim3 gN((N_NODES + TB - 1) / TB, 2);
    const dim3 gE((N_EDGES + TB - 1) / TB, 2);
    const int MB = (N_NODES + 127) / 128;   // 63

    init_kernel<<<gN, TB>>>();
    edge_kernel<<<gE, TB>>>(dmat[0], dmat[1], ei[0], ei[1]);
    dinv_kernel<<<gN, TB>>>();
    coeff_kernel<<<gE, TB>>>(ei[0], ei[1]);
    scan_kernel<<<2, 1024>>>();
    scatter_kernel<<<gE, TB>>>(ei[0], ei[1]);

    // GCN layer 1: t = x @ W1 ; h = relu(agg(t) + b1)
    fp16_gemm<false, false, false><<<dim3(F0 / 128, MB, 2), 256>>>(
        x_in[0], x_in[1], W1[0], W1[1], nullptr, nullptr, t[0], t[1],
        N_NODES, F0, F0);
    aggregate_kernel<<<dim3(N_NODES, 2), 128>>>(t[0], t[1], b1[0], b1[1], h[0], h[1]);

    // GCN layer 2
    fp16_gemm<false, false, false><<<dim3(F0 / 128, MB, 2), 256>>>(
        h[0], h[1], W2[0], W2[1], nullptr, nullptr, t[0], t[1],
        N_NODES, F0, F0);
    aggregate_kernel<<<dim3(N_NODES, 2), 128>>>(t[0], t[1], b2[0], b2[1], h[0], h[1]);

    // MLP: L1 fp16 (512->256), L2/L3 fp32
    fp16_gemm<false, true, true><<<dim3(256 / 128, MB, 2), 256>>>(
        h[0], h[1], L1w[0], L1w[1], L1b[0], L1b[1], m1[0], m1[1],
        N_NODES, 256, F0);
    gemm_kernel<64, 64, 16, 4, 4, true, true>
        <<<dim3(2, (N_NODES + 63) / 64, 2), 256>>>(
            m1[0], m1[1], L2w[0], L2w[1], L2b[0], L2b[1], m2[0], m2[1],
            N_NODES, 128, 256);
    gemm_kernel<64, 64, 16, 4, 4, true, true>
        <<<dim3(1, (N_NODES + 63) / 64, 2), 256>>>(
            m2[0], m2[1], L3w[0], L3w[1], L3b[0], L3b[1], m3[0], m3[1],
            N_NODES, 64, 128);

    // final (fp16, TRANSB): out = x64_m @ y64_d^T  [8000 x 8000]  (K=64 % 32 == 0)
    fp16_gemm<true, false, false><<<dim3((N_NODES + 127) / 128, MB, 1), 256>>>(
        m3[0], m3[0], m3[1], m3[1], nullptr, nullptr, out, out,
        N_NODES, N_NODES, 64);
}

// round 9
// speedup vs baseline: 1.2799x; 1.0125x over previous
#include <cuda_runtime.h>
#include <cuda_fp16.h>
#include <math.h>

#define N_NODES 8000
#define N_EDGES 256000
#define F0      512

// ---------------- scratch (static device allocations; no cudaMalloc) --------
__device__ float g_w    [2][N_EDGES];
__device__ float g_dinv [2][N_NODES];
__device__ int   g_hist [2][N_NODES];
__device__ int   g_offs [2][N_NODES + 1];
__device__ int   g_fill [2][N_NODES];
__device__ int   g_crow [2][N_EDGES];
__device__ float g_ccoef[2][N_EDGES];
__device__ float g_t    [2][N_NODES * F0];
__device__ float g_h    [2][N_NODES * F0];
__device__ float g_m1   [2][N_NODES * 256];
__device__ float g_m2   [2][N_NODES * 128];
__device__ float g_m3   [2][N_NODES * 64];

// ---------------- edge / degree prep (both graphs batched: blockIdx.y = g) --
__global__ void init_kernel() {
    int i = blockIdx.x * blockDim.x + threadIdx.x;
    int g = blockIdx.y;
    if (i < N_NODES) { g_dinv[g][i] = 1.0f; g_hist[g][i] = 0; }
}

__global__ void edge_kernel(const float* __restrict__ d0, const float* __restrict__ d1,
                            const int* __restrict__ e0, const int* __restrict__ e1) {
    int e = blockIdx.x * blockDim.x + threadIdx.x;
    int g = blockIdx.y;
    const float* data = g ? d1 : d0;
    const int*   ei   = g ? e1 : e0;
    if (e < N_EDGES) {
        int r = ei[e];
        int c = ei[N_EDGES + e];
        float v = fmaxf(data[(size_t)r * N_NODES + c], 0.0f);
        g_w[g][e] = v;
        atomicAdd(&g_dinv[g][c], v);
        atomicAdd(&g_hist[g][c], 1);
    }
}

// fused: exclusive scan of hist -> offs, plus dinv = rsqrt(deg). One block/graph.
__global__ void scan_dinv_kernel() {
    __shared__ int s[1024];
    int g = blockIdx.x;
    int t = threadIdx.x;
    // dinv first (independent of scan)
    for (int i = t; i < N_NODES; i += 1024)
        g_dinv[g][i] = rsqrtf(g_dinv[g][i]);   // deg >= 1 always
    int base = t * 8;
    int loc[8];
    int sum = 0;
#pragma unroll
    for (int j = 0; j < 8; j++) {
        int i = base + j;
        int v = (i < N_NODES) ? g_hist[g][i] : 0;
        loc[j] = sum;
        sum += v;
    }
    s[t] = sum;
    __syncthreads();
    for (int d = 1; d < 1024; d <<= 1) {
        int v = (t >= d) ? s[t - d] : 0;
        __syncthreads();
        s[t] += v;
        __syncthreads();
    }
    int cbase = s[t] - sum;
#pragma unroll
    for (int j = 0; j < 8; j++) {
        int i = base + j;
        if (i < N_NODES) {
            int o = cbase + loc[j];
            g_offs[g][i] = o;
            g_fill[g][i] = o;
        }
    }
    if (t == 0) g_offs[g][N_NODES] = N_EDGES;
}

// fused: coefficient compute + CSC scatter
__global__ void scatter_coeff_kernel(const int* __restrict__ e0, const int* __restrict__ e1) {
    int e = blockIdx.x * blockDim.x + threadIdx.x;
    int g = blockIdx.y;
    const int* ei = g ? e1 : e0;
    if (e < N_EDGES) {
        int r = ei[e];
        int c = ei[N_EDGES + e];
        float cf = g_dinv[g][r] * g_w[g][e] * g_dinv[g][c];
        int p = atomicAdd(&g_fill[g][c], 1);
        g_crow[g][p]  = r;
        g_ccoef[g][p] = cf;
    }
}

// ---------------- GCN aggregation (fp32 gather, fp32 accum) ------------------
__global__ void aggregate_kernel(const float* __restrict__ t0, const float* __restrict__ t1,
                                 const float* __restrict__ bias0, const float* __restrict__ bias1,
                                 float* __restrict__ o0, float* __restrict__ o1) {
    int c = blockIdx.x;
    int g = blockIdx.y;
    const float* t    = g ? t1 : t0;
    const float* bias = g ? bias1 : bias0;
    float* out        = g ? o1 : o0;
    const int* __restrict__ crow = g_crow[g];
    const float* __restrict__ ccoef = g_ccoef[g];
    int f = threadIdx.x * 4;
    float dv = g_dinv[g][c];
    float sc = dv * dv;
    float4 v = *reinterpret_cast<const float4*>(&t[(size_t)c * F0 + f]);
    float4 acc = make_float4(v.x * sc, v.y * sc, v.z * sc, v.w * sc);
    int e0 = g_offs[g][c], e1 = g_offs[g][c + 1];
#pragma unroll 4
    for (int e = e0; e < e1; e++) {
        int   r  = crow[e];
        float cf = ccoef[e];
        float4 u = *reinterpret_cast<const float4*>(&t[(size_t)r * F0 + f]);
        acc.x += cf * u.x; acc.y += cf * u.y; acc.z += cf * u.z; acc.w += cf * u.w;
    }
    float4 b = *reinterpret_cast<const float4*>(&bias[f]);
    acc.x = fmaxf(acc.x + b.x, 0.0f);
    acc.y = fmaxf(acc.y + b.y, 0.0f);
    acc.z = fmaxf(acc.z + b.z, 0.0f);
    acc.w = fmaxf(acc.w + b.w, 0.0f);
    *reinterpret_cast<float4*>(&out[(size_t)c * F0 + f]) = acc;
}

// ---------------- FP16 tensor-core GEMM -------------------------------------
// 128x128x32 tile, 256 threads, 2-stage SMEM double buffer, reg prefetch.
// C[Mn,Nn] = A[Mn,Kn] @ B  (B is [Kn,Nn] if !TRANSB else [Nn,Kn]); Kn % 32 == 0.
__device__ __forceinline__ unsigned packh2(float a, float b) {
    __half2 h = __floats2half2_rn(a, b);
    return *reinterpret_cast<unsigned*>(&h);
}

template <bool TRANSB, bool BIAS, bool RELU>
__global__ __launch_bounds__(256)
void fp16_gemm(const float* __restrict__ A0, const float* __restrict__ A1,
               const float* __restrict__ B0, const float* __restrict__ B1,
               const float* __restrict__ bias0, const float* __restrict__ bias1,
               float* __restrict__ C0, float* __restrict__ C1,
               int Mn, int Nn, int Kn) {
    constexpr int BM = 128, BN = 128, BK = 32;
    constexpr int LDA = BK / 2 + 4;   // 20 half2-words/row: conflict-free frags
    constexpr int LDB = BN + 8;       // 136 half2-words/row: conflict-free frags
    constexpr int ASZ = BM * LDA;
    constexpr int BSZ = (BK / 2) * LDB;
    __shared__ unsigned As[2 * ASZ];
    __shared__ unsigned Bs[2 * BSZ];

    const int gsel = blockIdx.z;
    const float* A    = gsel ? A1 : A0;
    const float* B    = gsel ? B1 : B0;
    const float* bias = gsel ? bias1 : bias0;
    float*       C    = gsel ? C1 : C0;

    const int tid  = threadIdx.x;
    const int lane = tid & 31;
    const int wid  = tid >> 5;
    const int wm   = (wid & 1) * 64;
    const int wn   = (wid >> 1) * 32;
    const int q    = lane >> 2;
    const int r    = lane & 3;
    const int m0   = blockIdx.y * BM;
    const int n0   = blockIdx.x * BN;

    float c[4][4][4];
#pragma unroll
    for (int i = 0; i < 4; i++)
#pragma unroll
        for (int j = 0; j < 4; j++)
#pragma unroll
            for (int k = 0; k < 4; k++) c[i][j][k] = 0.0f;

    float4 ra[4], rb[4];

    auto loadA = [&](int k0) {
#pragma unroll
        for (int i = 0; i < 4; i++) {
            int l = tid + i * 256;
            int row = l >> 3;
            int fq  = l & 7;
            float4 v = make_float4(0.f, 0.f, 0.f, 0.f);
            if (m0 + row < Mn)
                v = *reinterpret_cast<const float4*>(&A[(size_t)(m0 + row) * Kn + k0 + 4 * fq]);
            ra[i] = v;
        }
    };
    auto storeA = [&](int st) {
        unsigned* dst = As + st * ASZ;
#pragma unroll
        for (int i = 0; i < 4; i++) {
            int l = tid + i * 256;
            int row = l >> 3;
            int fq  = l & 7;
            dst[row * LDA + 2 * fq + 0] = packh2(ra[i].x, ra[i].y);
            dst[row * LDA + 2 * fq + 1] = packh2(ra[i].z, ra[i].w);
        }
    };
    auto loadB = [&](int k0) {
        if (!TRANSB) {
#pragma unroll
            for (int i = 0; i < 2; i++) {
                int p  = tid + i * 256;
                int kp = p >> 5;
                int nq = (p & 31) << 2;
                float4 lo = make_float4(0.f, 0.f, 0.f, 0.f);
                float4 hi = make_float4(0.f, 0.f, 0.f, 0.f);
                if (n0 + nq < Nn) {
                    lo = *reinterpret_cast<const float4*>(&B[(size_t)(k0 + 2 * kp)     * Nn + n0 + nq]);
                    hi = *reinterpret_cast<const float4*>(&B[(size_t)(k0 + 2 * kp + 1) * Nn + n0 + nq]);
                }
                rb[2 * i + 0] = lo;
                rb[2 * i + 1] = hi;
            }
        } else {
#pragma unroll
            for (int i = 0; i < 4; i++) {
                int l = tid + i * 256;
                int n  = l >> 3;
                int fq = l & 7;
                float4 v = make_float4(0.f, 0.f, 0.f, 0.f);
                if (n0 + n < Nn)
                    v = *reinterpret_cast<const float4*>(&B[(size_t)(n0 + n) * Kn + k0 + 4 * fq]);
                rb[i] = v;
            }
        }
    };
    auto storeB = [&](int st) {
        unsigned* dst = Bs + st * BSZ;
        if (!TRANSB) {
#pragma unroll
            for (int i = 0; i < 2; i++) {
                int p  = tid + i * 256;
                int kp = p >> 5;
                int nq = (p & 31) << 2;
                float4 lo = rb[2 * i + 0];
                float4 hi = rb[2 * i + 1];
                dst[kp * LDB + nq + 0] = packh2(lo.x, hi.x);
                dst[kp * LDB + nq + 1] = packh2(lo.y, hi.y);
                dst[kp * LDB + nq + 2] = packh2(lo.z, hi.z);
                dst[kp * LDB + nq + 3] = packh2(lo.w, hi.w);
            }
        } else {
#pragma unroll
            for (int i = 0; i < 4; i++) {
                int l = tid + i * 256;
                int n  = l >> 3;
                int fq = l & 7;
                float4 v = rb[i];
                dst[(2 * fq + 0) * LDB + n] = packh2(v.x, v.y);
                dst[(2 * fq + 1) * LDB + n] = packh2(v.z, v.w);
            }
        }
    };
    auto compute = [&](int st) {
        const unsigned* as = As + st * ASZ;
        const unsigned* bs = Bs + st * BSZ;
#pragma unroll
        for (int ks = 0; ks < BK / 2; ks += 8) {
            unsigned a[4][4], b[4][2];
#pragma unroll
            for (int tm = 0; tm < 4; tm++) {
                int row = wm + tm * 16 + q;
                a[tm][0] = as[(row)     * LDA + ks + r];
                a[tm][1] = as[(row + 8) * LDA + ks + r];
                a[tm][2] = as[(row)     * LDA + ks + 4 + r];
                a[tm][3] = as[(row + 8) * LDA + ks + 4 + r];
            }
#pragma unroll
            for (int tn = 0; tn < 4; tn++) {
                int col = wn + tn * 8 + q;
                b[tn][0] = bs[(ks + r)     * LDB + col];
                b[tn][1] = bs[(ks + 4 + r) * LDB + col];
            }
#pragma unroll
            for (int tm = 0; tm < 4; tm++)
#pragma unroll
                for (int tn = 0; tn < 4; tn++) {
                    asm volatile(
                        "mma.sync.aligned.m16n8k16.row.col.f32.f16.f16.f32 "
                        "{%0,%1,%2,%3}, {%4,%5,%6,%7}, {%8,%9}, {%0,%1,%2,%3};"
                        : "+f"(c[tm][tn][0]), "+f"(c[tm][tn][1]),
                          "+f"(c[tm][tn][2]), "+f"(c[tm][tn][3])
                        : "r"(a[tm][0]), "r"(a[tm][1]), "r"(a[tm][2]), "r"(a[tm][3]),
                          "r"(b[tn][0]), "r"(b[tn][1]));
                }
        }
    };

    // prologue: stage 0 filled
    loadA(0); loadB(0);
    storeA(0); storeB(0);

    int s = 0;
    for (int k0 = 0; k0 < Kn; k0 += BK, s ^= 1) {
        __syncthreads();                 // stage s ready for all warps
        bool next = (k0 + BK) < Kn;
        if (next) { loadA(k0 + BK); loadB(k0 + BK); }  // global->regs (latency hidden by compute)
        compute(s);
        if (next) { storeA(s ^ 1); storeB(s ^ 1); }    // regs->smem into idle stage
    }

    // epilogue
#pragma unroll
    for (int tm = 0; tm < 4; tm++) {
        int row = m0 + wm + tm * 16 + q;
#pragma unroll
        for (int tn = 0; tn < 4; tn++) {
            int col = n0 + wn + tn * 8 + 2 * r;
            if (col >= Nn) continue;
            float v0 = c[tm][tn][0], v1 = c[tm][tn][1];
            float v2 = c[tm][tn][2], v3 = c[tm][tn][3];
            if (BIAS) {
                float bb0 = bias[col], bb1 = bias[col + 1];
                v0 += bb0; v1 += bb1; v2 += bb0; v3 += bb1;
            }
            if (RELU) {
                v0 = fmaxf(v0, 0.f); v1 = fmaxf(v1, 0.f);
                v2 = fmaxf(v2, 0.f); v3 = fmaxf(v3, 0.f);
            }
            if (row < Mn)
                *reinterpret_cast<float2*>(&C[(size_t)row * Nn + col]) = make_float2(v0, v1);
            if (row + 8 < Mn)
                *reinterpret_cast<float2*>(&C[(size_t)(row + 8) * Nn + col]) = make_float2(v2, v3);
        }
    }
}

// ---------------- fp32 GEMM for narrow MLP layers (blockIdx.z = g) -----------
template <int BM, int BN, int BK, int TM, int TN, bool BIAS, bool RELU>
__global__ __launch_bounds__((BM / TM) * (BN / TN))
void gemm_kernel(const float* __restrict__ A0, const float* __restrict__ A1,
                 const float* __restrict__ B0, const float* __restrict__ B1,
                 const float* __restrict__ bias0, const float* __restrict__ bias1,
                 float* __restrict__ C0, float* __restrict__ C1,
                 int Mn, int Nn, int Kn) {
    constexpr int THREADS = (BM / TM) * (BN / TN);
    __shared__ float As[BK][BM];
    __shared__ float Bs[BK][BN];
    const int gsel = blockIdx.z;
    const float* A    = gsel ? A1 : A0;
    const float* B    = gsel ? B1 : B0;
    const float* bias = gsel ? bias1 : bias0;
    float*       C    = gsel ? C1 : C0;
    const int tid = threadIdx.x;
    const int tx = tid % (BN / TN);
    const int ty = tid / (BN / TN);
    const int m0 = blockIdx.y * BM;
    const int n0 = blockIdx.x * BN;

    float acc[TM][TN];
#pragma unroll
    for (int i = 0; i < TM; i++)
#pragma unroll
        for (int j = 0; j < TN; j++) acc[i][j] = 0.0f;

    for (int k0 = 0; k0 < Kn; k0 += BK) {
#pragma unroll
        for (int l = tid; l < BM * BK / 4; l += THREADS) {
            int row = l / (BK / 4);
            int kq  = (l % (BK / 4)) * 4;
            float4 v = make_float4(0.f, 0.f, 0.f, 0.f);
            if (m0 + row < Mn)
                v = *reinterpret_cast<const float4*>(&A[(size_t)(m0 + row) * Kn + k0 + kq]);
            As[kq + 0][row] = v.x; As[kq + 1][row] = v.y;
            As[kq + 2][row] = v.z; As[kq + 3][row] = v.w;
        }
#pragma unroll
        for (int l = tid; l < BK * BN / 4; l += THREADS) {
            int kk = l / (BN / 4);
            int nq = (l % (BN / 4)) * 4;
            float4 v = make_float4(0.f, 0.f, 0.f, 0.f);
            if (n0 + nq < Nn)
                v = *reinterpret_cast<const float4*>(&B[(size_t)(k0 + kk) * Nn + n0 + nq]);
            *reinterpret_cast<float4*>(&Bs[kk][nq]) = v;
        }
        __syncthreads();
#pragma unroll
        for (int k = 0; k < BK; k++) {
            float a[TM], b[TN];
#pragma unroll
            for (int i = 0; i < TM; i++) a[i] = As[k][ty * TM + i];
#pragma unroll
            for (int j = 0; j < TN; j++) b[j] = Bs[k][tx * TN + j];
#pragma unroll
            for (int i = 0; i < TM; i++)
#pragma unroll
                for (int j = 0; j < TN; j++) acc[i][j] += a[i] * b[j];
        }
        __syncthreads();
    }
#pragma unroll
    for (int i = 0; i < TM; i++) {
        int m = m0 + ty * TM + i;
        if (m >= Mn) continue;
#pragma unroll
        for (int j = 0; j < TN; j += 4) {
            int n = n0 + tx * TN + j;
            if (n >= Nn) continue;
            float4 v = make_float4(acc[i][j], acc[i][j + 1], acc[i][j + 2], acc[i][j + 3]);
            if (BIAS) {
                v.x += bias[n]; v.y += bias[n + 1]; v.z += bias[n + 2]; v.w += bias[n + 3];
            }
            if (RELU) {
                v.x = fmaxf(v.x, 0.f); v.y = fmaxf(v.y, 0.f);
                v.z = fmaxf(v.z, 0.f); v.w = fmaxf(v.w, 0.f);
            }
            *reinterpret_cast<float4*>(&C[(size_t)m * Nn + n]) = v;
        }
    }
}

// ---------------- host-side orchestration -----------------------------------
extern "C" void kernel_launch(void* const* d_in, const int* in_sizes, int n_in,
                              void* d_out, int out_size) {
    const float* x_in[2]  = { (const float*)d_in[0], (const float*)d_in[1] };
    const float* dmat[2]  = { (const float*)d_in[2], (const float*)d_in[3] };
    const int*   ei[2]    = { (const int*)d_in[4],   (const int*)d_in[5]   };
    const float* W1[2]    = { (const float*)d_in[6],  (const float*)d_in[10] };
    const float* b1[2]    = { (const float*)d_in[7],  (const float*)d_in[11] };
    const float* W2[2]    = { (const float*)d_in[8],  (const float*)d_in[12] };
    const float* b2[2]    = { (const float*)d_in[9],  (const float*)d_in[13] };
    const float* L1w[2]   = { (const float*)d_in[14], (const float*)d_in[20] };
    const float* L1b[2]   = { (const float*)d_in[15], (const float*)d_in[21] };
    const float* L2w[2]   = { (const float*)d_in[16], (const float*)d_in[22] };
    const float* L2b[2]   = { (const float*)d_in[17], (const float*)d_in[23] };
    const float* L3w[2]   = { (const float*)d_in[18], (const float*)d_in[24] };
    const float* L3b[2]   = { (const float*)d_in[19], (const float*)d_in[25] };
    float* out = (float*)d_out;

    float *p_t, *p_h, *p_m1, *p_m2, *p_m3;
    cudaGetSymbolAddress((void**)&p_t,  g_t);
    cudaGetSymbolAddress((void**)&p_h,  g_h);
    cudaGetSymbolAddress((void**)&p_m1, g_m1);
    cudaGetSymbolAddress((void**)&p_m2, g_m2);
    cudaGetSymbolAddress((void**)&p_m3, g_m3);

    float* t[2]  = { p_t,  p_t  + (size_t)N_NODES * F0 };
    float* h[2]  = { p_h,  p_h  + (size_t)N_NODES * F0 };
    float* m1[2] = { p_m1, p_m1 + (size_t)N_NODES * 256 };
    float* m2[2] = { p_m2, p_m2 + (size_t)N_NODES * 128 };
    float* m3[2] = { p_m3, p_m3 + (size_t)N_NODES * 64 };

    const int TB = 256;
    const dim3 gN((N_NODES + TB - 1) / TB, 2);
    const dim3 gE((N_EDGES + TB - 1) / TB, 2);
    const int MB = (N_NODES + 127) / 128;   // 63

    // launches 1-3: prep that GEMM1 does not depend on is interleaved AFTER
    // GEMM1 so the ncu capture slot (4th launch) lands on fp16_gemm.
    init_kernel<<<gN, TB>>>();
    edge_kernel<<<gE, TB>>>(dmat[0], dmat[1], ei[0], ei[1]);
    scan_dinv_kernel<<<2, 1024>>>();

    // launch 4 (ncu capture slot): GCN layer-1 GEMM  t = x @ W1
    fp16_gemm<false, false, false><<<dim3(F0 / 128, MB, 2), 256>>>(
        x_in[0], x_in[1], W1[0], W1[1], nullptr, nullptr, t[0], t[1],
        N_NODES, F0, F0);

    // launch 5: finish edge prep (needed before aggregation only)
    scatter_coeff_kernel<<<gE, TB>>>(ei[0], ei[1]);

    aggregate_kernel<<<dim3(N_NODES, 2), 128>>>(t[0], t[1], b1[0], b1[1], h[0], h[1]);

    // GCN layer 2
    fp16_gemm<false, false, false><<<dim3(F0 / 128, MB, 2), 256>>>(
        h[0], h[1], W2[0], W2[1], nullptr, nullptr, t[0], t[1],
        N_NODES, F0, F0);
    aggregate_kernel<<<dim3(N_NODES, 2), 128>>>(t[0], t[1], b2[0], b2[1], h[0], h[1]);

    // MLP: L1 fp16 (512->256), L2/L3 fp32
    fp16_gemm<false, true, true><<<dim3(256 / 128, MB, 2), 256>>>(
        h[0], h[1], L1w[0], L1w[1], L1b[0], L1b[1], m1[0], m1[1],
        N_NODES, 256, F0);
    gemm_kernel<64, 64, 16, 4, 4, true, true>
        <<<dim3(2, (N_NODES + 63) / 64, 2), 256>>>(
            m1[0], m1[1], L2w[0], L2w[1], L2b[0], L2b[1], m2[0], m2[1],
            N_NODES, 128, 256);
    gemm_kernel<64, 64, 16, 4, 4, true, true>
        <<<dim3(1, (N_NODES + 63) / 64, 2), 256>>>(
            m2[0], m2[1], L3w[0], L3w[1], L3b[0], L3b[1], m3[0], m3[1],
            N_NODES, 64, 128);

    // final (fp16, TRANSB): out = x64_m @ y64_d^T  [8000 x 8000]
    fp16_gemm<true, false, false><<<dim3((N_NODES + 127) / 128, MB, 1), 256>>>(
        m3[0], m3[0], m3[1], m3[1], nullptr, nullptr, out, out,
        N_NODES, N_NODES, 64);
}

// round 10
// speedup vs baseline: 1.3226x; 1.0333x over previous
#include <cuda_runtime.h>
#include <cuda_fp16.h>
#include <math.h>

#define N_NODES 8000
#define N_EDGES 256000
#define F0      512

// ---------------- scratch (static device allocations; no cudaMalloc) --------
__device__ float g_w    [2][N_EDGES];
__device__ float g_dinv [2][N_NODES];
__device__ int   g_hist [2][N_NODES];
__device__ int   g_offs [2][N_NODES + 1];
__device__ int   g_fill [2][N_NODES];
__device__ int   g_crow [2][N_EDGES];
__device__ float g_ccoef[2][N_EDGES];
__device__ float g_t    [2][N_NODES * F0];
__device__ float g_h    [2][N_NODES * F0];
__device__ float g_m1   [2][N_NODES * 256];
__device__ float g_m2   [2][N_NODES * 128];
__device__ float g_m3   [2][N_NODES * 64];

// ---------------- edge / degree prep (both graphs batched: blockIdx.y = g) --
__global__ void init_kernel() {
    int i = blockIdx.x * blockDim.x + threadIdx.x;
    int g = blockIdx.y;
    if (i < N_NODES) { g_dinv[g][i] = 1.0f; g_hist[g][i] = 0; }
}

__global__ void edge_kernel(const float* __restrict__ d0, const float* __restrict__ d1,
                            const int* __restrict__ e0, const int* __restrict__ e1) {
    int e = blockIdx.x * blockDim.x + threadIdx.x;
    int g = blockIdx.y;
    const float* data = g ? d1 : d0;
    const int*   ei   = g ? e1 : e0;
    if (e < N_EDGES) {
        int r = ei[e];
        int c = ei[N_EDGES + e];
        float v = fmaxf(data[(size_t)r * N_NODES + c], 0.0f);
        g_w[g][e] = v;
        atomicAdd(&g_dinv[g][c], v);
        atomicAdd(&g_hist[g][c], 1);
    }
}

// fused: exclusive scan of hist -> offs, plus dinv = rsqrt(deg). One block/graph.
__global__ void scan_dinv_kernel() {
    __shared__ int s[1024];
    int g = blockIdx.x;
    int t = threadIdx.x;
    for (int i = t; i < N_NODES; i += 1024)
        g_dinv[g][i] = rsqrtf(g_dinv[g][i]);   // deg >= 1 always
    int base = t * 8;
    int loc[8];
    int sum = 0;
#pragma unroll
    for (int j = 0; j < 8; j++) {
        int i = base + j;
        int v = (i < N_NODES) ? g_hist[g][i] : 0;
        loc[j] = sum;
        sum += v;
    }
    s[t] = sum;
    __syncthreads();
    for (int d = 1; d < 1024; d <<= 1) {
        int v = (t >= d) ? s[t - d] : 0;
        __syncthreads();
        s[t] += v;
        __syncthreads();
    }
    int cbase = s[t] - sum;
#pragma unroll
    for (int j = 0; j < 8; j++) {
        int i = base + j;
        if (i < N_NODES) {
            int o = cbase + loc[j];
            g_offs[g][i] = o;
            g_fill[g][i] = o;
        }
    }
    if (t == 0) g_offs[g][N_NODES] = N_EDGES;
}

// fused: coefficient compute + CSC scatter
__global__ void scatter_coeff_kernel(const int* __restrict__ e0, const int* __restrict__ e1) {
    int e = blockIdx.x * blockDim.x + threadIdx.x;
    int g = blockIdx.y;
    const int* ei = g ? e1 : e0;
    if (e < N_EDGES) {
        int r = ei[e];
        int c = ei[N_EDGES + e];
        float cf = g_dinv[g][r] * g_w[g][e] * g_dinv[g][c];
        int p = atomicAdd(&g_fill[g][c], 1);
        g_crow[g][p]  = r;
        g_ccoef[g][p] = cf;
    }
}

// ---------------- GCN aggregation (fp32 gather, fp32 accum) ------------------
__global__ void aggregate_kernel(const float* __restrict__ t0, const float* __restrict__ t1,
                                 const float* __restrict__ bias0, const float* __restrict__ bias1,
                                 float* __restrict__ o0, float* __restrict__ o1) {
    int c = blockIdx.x;
    int g = blockIdx.y;
    const float* t    = g ? t1 : t0;
    const float* bias = g ? bias1 : bias0;
    float* out        = g ? o1 : o0;
    const int* __restrict__ crow = g_crow[g];
    const float* __restrict__ ccoef = g_ccoef[g];
    int f = threadIdx.x * 4;
    float dv = g_dinv[g][c];
    float sc = dv * dv;
    float4 v = *reinterpret_cast<const float4*>(&t[(size_t)c * F0 + f]);
    float4 acc = make_float4(v.x * sc, v.y * sc, v.z * sc, v.w * sc);
    int e0 = g_offs[g][c], e1 = g_offs[g][c + 1];
#pragma unroll 4
    for (int e = e0; e < e1; e++) {
        int   r  = crow[e];
        float cf = ccoef[e];
        float4 u = *reinterpret_cast<const float4*>(&t[(size_t)r * F0 + f]);
        acc.x += cf * u.x; acc.y += cf * u.y; acc.z += cf * u.z; acc.w += cf * u.w;
    }
    float4 b = *reinterpret_cast<const float4*>(&bias[f]);
    acc.x = fmaxf(acc.x + b.x, 0.0f);
    acc.y = fmaxf(acc.y + b.y, 0.0f);
    acc.z = fmaxf(acc.z + b.z, 0.0f);
    acc.w = fmaxf(acc.w + b.w, 0.0f);
    *reinterpret_cast<float4*>(&out[(size_t)c * F0 + f]) = acc;
}

// ---------------- FP16 tensor-core GEMM (ldmatrix fragment feed) -------------
// 128x128x32 tile, 256 threads, 2-stage SMEM double buffer, reg prefetch.
// C[Mn,Nn] = A[Mn,Kn] @ B  (B is [Kn,Nn] if !TRANSB else [Nn,Kn]); Kn % 32 == 0.
__device__ __forceinline__ unsigned packh2(float a, float b) {
    __half2 h = __floats2half2_rn(a, b);
    return *reinterpret_cast<unsigned*>(&h);
}
__device__ __forceinline__ void ldsm_x4(unsigned& r0, unsigned& r1,
                                        unsigned& r2, unsigned& r3, unsigned addr) {
    asm volatile("ldmatrix.sync.aligned.m8n8.x4.shared.b16 {%0,%1,%2,%3}, [%4];"
                 : "=r"(r0), "=r"(r1), "=r"(r2), "=r"(r3) : "r"(addr));
}
__device__ __forceinline__ void ldsm_x4_trans(unsigned& r0, unsigned& r1,
                                              unsigned& r2, unsigned& r3, unsigned addr) {
    asm volatile("ldmatrix.sync.aligned.m8n8.x4.trans.shared.b16 {%0,%1,%2,%3}, [%4];"
                 : "=r"(r0), "=r"(r1), "=r"(r2), "=r"(r3) : "r"(addr));
}

template <bool TRANSB, bool BIAS, bool RELU>
__global__ __launch_bounds__(256)
void fp16_gemm(const float* __restrict__ A0, const float* __restrict__ A1,
               const float* __restrict__ B0, const float* __restrict__ B1,
               const float* __restrict__ bias0, const float* __restrict__ bias1,
               float* __restrict__ C0, float* __restrict__ C1,
               int Mn, int Nn, int Kn) {
    constexpr int BM = 128, BN = 128, BK = 32;
    constexpr int LDA  = BK / 2 + 4;  // A rows: 20 half2-words = 80B (ldsm conflict-free)
    constexpr int LDB2 = BK / 2 + 4;  // TRANSB: B as [n][kpair], 80B rows
    constexpr int LDBH = BN + 8;      // !TRANSB: B as [k][n] halves, 272B rows (conflict-free)
    constexpr int ASZ = BM * LDA;                      // words
    constexpr int BSZ = TRANSB ? (BN * LDB2) : (BK * LDBH / 2);  // words
    __shared__ unsigned As[2 * ASZ];
    __shared__ unsigned Bs[2 * BSZ];

    const int gsel = blockIdx.z;
    const float* A    = gsel ? A1 : A0;
    const float* B    = gsel ? B1 : B0;
    const float* bias = gsel ? bias1 : bias0;
    float*       C    = gsel ? C1 : C0;

    const int tid  = threadIdx.x;
    const int lane = tid & 31;
    const int wid  = tid >> 5;
    const int wm   = (wid & 1) * 64;
    const int wn   = (wid >> 1) * 32;
    const int q    = lane >> 2;
    const int r    = lane & 3;
    const int m0   = blockIdx.y * BM;
    const int n0   = blockIdx.x * BN;

    // ldmatrix per-lane address components
    const int la_row  = ((lane >> 3) & 1) * 8 + (lane & 7);   // A: row within 16-row tile
    const int la_koff = ((lane >> 4) & 1) * 4;                // A: word offset within k-step
    const int lbt_row = ((lane >> 4) & 1) * 8 + (lane & 7);   // B TRANSB: n-row within tn-pair
    const int lbt_koff= ((lane >> 3) & 1) * 4;                // B TRANSB: word offset
    const int lbn_k   = ((lane >> 3) & 1) * 8 + (lane & 7);   // B !TRANSB: k-row offset
    const int lbn_n   = ((lane >> 4) & 1) * 8;                // B !TRANSB: n offset in tn-pair

    const unsigned as_base = (unsigned)__cvta_generic_to_shared(As);
    const unsigned bs_base = (unsigned)__cvta_generic_to_shared(Bs);

    float c[4][4][4];
#pragma unroll
    for (int i = 0; i < 4; i++)
#pragma unroll
        for (int j = 0; j < 4; j++)
#pragma unroll
            for (int k = 0; k < 4; k++) c[i][j][k] = 0.0f;

    float4 ra[4], rb[4];

    auto loadA = [&](int k0) {
#pragma unroll
        for (int i = 0; i < 4; i++) {
            int l = tid + i * 256;
            int row = l >> 3;
            int fq  = l & 7;
            float4 v = make_float4(0.f, 0.f, 0.f, 0.f);
            if (m0 + row < Mn)
                v = *reinterpret_cast<const float4*>(&A[(size_t)(m0 + row) * Kn + k0 + 4 * fq]);
            ra[i] = v;
        }
    };
    auto storeA = [&](int st) {
        unsigned* dst = As + st * ASZ;
#pragma unroll
        for (int i = 0; i < 4; i++) {
            int l = tid + i * 256;
            int row = l >> 3;
            int fq  = l & 7;
            *reinterpret_cast<uint2*>(&dst[row * LDA + 2 * fq]) =
                make_uint2(packh2(ra[i].x, ra[i].y), packh2(ra[i].z, ra[i].w));
        }
    };
    auto loadB = [&](int k0) {
        if (!TRANSB) {
            // [Kn][Nn]: 32 k-rows x 32 float4 chunks = 1024 tasks, 4/thread
#pragma unroll
            for (int i = 0; i < 4; i++) {
                int l = tid + i * 256;
                int k  = l >> 5;
                int nq = (l & 31) << 2;
                float4 v = make_float4(0.f, 0.f, 0.f, 0.f);
                if (n0 + nq < Nn)
                    v = *reinterpret_cast<const float4*>(&B[(size_t)(k0 + k) * Nn + n0 + nq]);
                rb[i] = v;
            }
        } else {
            // [Nn][Kn]: 128 n-rows x 8 float4 = 1024 tasks, 4/thread
#pragma unroll
            for (int i = 0; i < 4; i++) {
                int l = tid + i * 256;
                int n  = l >> 3;
                int fq = l & 7;
                float4 v = make_float4(0.f, 0.f, 0.f, 0.f);
                if (n0 + n < Nn)
                    v = *reinterpret_cast<const float4*>(&B[(size_t)(n0 + n) * Kn + k0 + 4 * fq]);
                rb[i] = v;
            }
        }
    };
    auto storeB = [&](int st) {
        unsigned* dst = Bs + st * BSZ;
        if (!TRANSB) {
            __half* dh = reinterpret_cast<__half*>(dst);
#pragma unroll
            for (int i = 0; i < 4; i++) {
                int l = tid + i * 256;
                int k  = l >> 5;
                int nq = (l & 31) << 2;
                *reinterpret_cast<uint2*>(&dh[k * LDBH + nq]) =
                    make_uint2(packh2(rb[i].x, rb[i].y), packh2(rb[i].z, rb[i].w));
            }
        } else {
#pragma unroll
            for (int i = 0; i < 4; i++) {
                int l = tid + i * 256;
                int n  = l >> 3;
                int fq = l & 7;
                *reinterpret_cast<uint2*>(&dst[n * LDB2 + 2 * fq]) =
                    make_uint2(packh2(rb[i].x, rb[i].y), packh2(rb[i].z, rb[i].w));
            }
        }
    };
    auto compute = [&](int st) {
        const unsigned a_st = as_base + st * ASZ * 4;
        const unsigned b_st = bs_base + st * BSZ * 4;
#pragma unroll
        for (int ks = 0; ks < BK / 2; ks += 8) {
            unsigned a[4][4], b[4][2];
#pragma unroll
            for (int tm = 0; tm < 4; tm++) {
                unsigned addr = a_st +
                    ((unsigned)((wm + tm * 16 + la_row) * LDA + ks + la_koff) << 2);
                ldsm_x4(a[tm][0], a[tm][1], a[tm][2], a[tm][3], addr);
            }
            if (!TRANSB) {
#pragma unroll
                for (int tp = 0; tp < 2; tp++) {   // tn pairs {0,1}, {2,3}
                    unsigned addr = b_st +
                        ((unsigned)((2 * ks + lbn_k) * LDBH + wn + tp * 16 + lbn_n) << 1);
                    ldsm_x4_trans(b[2 * tp][0], b[2 * tp][1],
                                  b[2 * tp + 1][0], b[2 * tp + 1][1], addr);
                }
            } else {
#pragma unroll
                for (int tp = 0; tp < 2; tp++) {
                    unsigned addr = b_st +
                        ((unsigned)((wn + tp * 16 + lbt_row) * LDB2 + ks + lbt_koff) << 2);
                    ldsm_x4(b[2 * tp][0], b[2 * tp][1],
                            b[2 * tp + 1][0], b[2 * tp + 1][1], addr);
                }
            }
#pragma unroll
            for (int tm = 0; tm < 4; tm++)
#pragma unroll
                for (int tn = 0; tn < 4; tn++) {
                    asm volatile(
                        "mma.sync.aligned.m16n8k16.row.col.f32.f16.f16.f32 "
                        "{%0,%1,%2,%3}, {%4,%5,%6,%7}, {%8,%9}, {%0,%1,%2,%3};"
                        : "+f"(c[tm][tn][0]), "+f"(c[tm][tn][1]),
                          "+f"(c[tm][tn][2]), "+f"(c[tm][tn][3])
                        : "r"(a[tm][0]), "r"(a[tm][1]), "r"(a[tm][2]), "r"(a[tm][3]),
                          "r"(b[tn][0]), "r"(b[tn][1]));
                }
        }
    };

    // prologue
    loadA(0); loadB(0);
    storeA(0); storeB(0);

    int s = 0;
    for (int k0 = 0; k0 < Kn; k0 += BK, s ^= 1) {
        __syncthreads();
        bool next = (k0 + BK) < Kn;
        if (next) { loadA(k0 + BK); loadB(k0 + BK); }
        compute(s);
        if (next) { storeA(s ^ 1); storeB(s ^ 1); }
    }

    // epilogue
#pragma unroll
    for (int tm = 0; tm < 4; tm++) {
        int row = m0 + wm + tm * 16 + q;
#pragma unroll
        for (int tn = 0; tn < 4; tn++) {
            int col = n0 + wn + tn * 8 + 2 * r;
            if (col >= Nn) continue;
            float v0 = c[tm][tn][0], v1 = c[tm][tn][1];
            float v2 = c[tm][tn][2], v3 = c[tm][tn][3];
            if (BIAS) {
                float bb0 = bias[col], bb1 = bias[col + 1];
                v0 += bb0; v1 += bb1; v2 += bb0; v3 += bb1;
            }
            if (RELU) {
                v0 = fmaxf(v0, 0.f); v1 = fmaxf(v1, 0.f);
                v2 = fmaxf(v2, 0.f); v3 = fmaxf(v3, 0.f);
            }
            if (row < Mn)
                *reinterpret_cast<float2*>(&C[(size_t)row * Nn + col]) = make_float2(v0, v1);
            if (row + 8 < Mn)
                *reinterpret_cast<float2*>(&C[(size_t)(row + 8) * Nn + col]) = make_float2(v2, v3);
        }
    }
}

// ---------------- fp32 GEMM for narrow MLP layers (blockIdx.z = g) -----------
template <int BM, int BN, int BK, int TM, int TN, bool BIAS, bool RELU>
__global__ __launch_bounds__((BM / TM) * (BN / TN))
void gemm_kernel(const float* __restrict__ A0, const float* __restrict__ A1,
                 const float* __restrict__ B0, const float* __restrict__ B1,
                 const float* __restrict__ bias0, const float* __restrict__ bias1,
                 float* __restrict__ C0, float* __restrict__ C1,
                 int Mn, int Nn, int Kn) {
    constexpr int THREADS = (BM / TM) * (BN / TN);
    __shared__ float As[BK][BM];
    __shared__ float Bs[BK][BN];
    const int gsel = blockIdx.z;
    const float* A    = gsel ? A1 : A0;
    const float* B    = gsel ? B1 : B0;
    const float* bias = gsel ? bias1 : bias0;
    float*       C    = gsel ? C1 : C0;
    const int tid = threadIdx.x;
    const int tx = tid % (BN / TN);
    const int ty = tid / (BN / TN);
    const int m0 = blockIdx.y * BM;
    const int n0 = blockIdx.x * BN;

    float acc[TM][TN];
#pragma unroll
    for (int i = 0; i < TM; i++)
#pragma unroll
        for (int j = 0; j < TN; j++) acc[i][j] = 0.0f;

    for (int k0 = 0; k0 < Kn; k0 += BK) {
#pragma unroll
        for (int l = tid; l < BM * BK / 4; l += THREADS) {
            int row = l / (BK / 4);
            int kq  = (l % (BK / 4)) * 4;
            float4 v = make_float4(0.f, 0.f, 0.f, 0.f);
            if (m0 + row < Mn)
                v = *reinterpret_cast<const float4*>(&A[(size_t)(m0 + row) * Kn + k0 + kq]);
            As[kq + 0][row] = v.x; As[kq + 1][row] = v.y;
            As[kq + 2][row] = v.z; As[kq + 3][row] = v.w;
        }
#pragma unroll
        for (int l = tid; l < BK * BN / 4; l += THREADS) {
            int kk = l / (BN / 4);
            int nq = (l % (BN / 4)) * 4;
            float4 v = make_float4(0.f, 0.f, 0.f, 0.f);
            if (n0 + nq < Nn)
                v = *reinterpret_cast<const float4*>(&B[(size_t)(k0 + kk) * Nn + n0 + nq]);
            *reinterpret_cast<float4*>(&Bs[kk][nq]) = v;
        }
        __syncthreads();
#pragma unroll
        for (int k = 0; k < BK; k++) {
            float a[TM], b[TN];
#pragma unroll
            for (int i = 0; i < TM; i++) a[i] = As[k][ty * TM + i];
#pragma unroll
            for (int j = 0; j < TN; j++) b[j] = Bs[k][tx * TN + j];
#pragma unroll
            for (int i = 0; i < TM; i++)
#pragma unroll
                for (int j = 0; j < TN; j++) acc[i][j] += a[i] * b[j];
        }
        __syncthreads();
    }
#pragma unroll
    for (int i = 0; i < TM; i++) {
        int m = m0 + ty * TM + i;
        if (m >= Mn) continue;
#pragma unroll
        for (int j = 0; j < TN; j += 4) {
            int n = n0 + tx * TN + j;
            if (n >= Nn) continue;
            float4 v = make_float4(acc[i][j], acc[i][j + 1], acc[i][j + 2], acc[i][j + 3]);
            if (BIAS) {
                v.x += bias[n]; v.y += bias[n + 1]; v.z += bias[n + 2]; v.w += bias[n + 3];
            }
            if (RELU) {
                v.x = fmaxf(v.x, 0.f); v.y = fmaxf(v.y, 0.f);
                v.z = fmaxf(v.z, 0.f); v.w = fmaxf(v.w, 0.f);
            }
            *reinterpret_cast<float4*>(&C[(size_t)m * Nn + n]) = v;
        }
    }
}

// ---------------- host-side orchestration -----------------------------------
extern "C" void kernel_launch(void* const* d_in, const int* in_sizes, int n_in,
                              void* d_out, int out_size) {
    const float* x_in[2]  = { (const float*)d_in[0], (const float*)d_in[1] };
    const float* dmat[2]  = { (const float*)d_in[2], (const float*)d_in[3] };
    const int*   ei[2]    = { (const int*)d_in[4],   (const int*)d_in[5]   };
    const float* W1[2]    = { (const float*)d_in[6],  (const float*)d_in[10] };
    const float* b1[2]    = { (const float*)d_in[7],  (const float*)d_in[11] };
    const float* W2[2]    = { (const float*)d_in[8],  (const float*)d_in[12] };
    const float* b2[2]    = { (const float*)d_in[9],  (const float*)d_in[13] };
    const float* L1w[2]   = { (const float*)d_in[14], (const float*)d_in[20] };
    const float* L1b[2]   = { (const float*)d_in[15], (const float*)d_in[21] };
    const float* L2w[2]   = { (const float*)d_in[16], (const float*)d_in[22] };
    const float* L2b[2]   = { (const float*)d_in[17], (const float*)d_in[23] };
    const float* L3w[2]   = { (const float*)d_in[18], (const float*)d_in[24] };
    const float* L3b[2]   = { (const float*)d_in[19], (const float*)d_in[25] };
    float* out = (float*)d_out;

    float *p_t, *p_h, *p_m1, *p_m2, *p_m3;
    cudaGetSymbolAddress((void**)&p_t,  g_t);
    cudaGetSymbolAddress((void**)&p_h,  g_h);
    cudaGetSymbolAddress((void**)&p_m1, g_m1);
    cudaGetSymbolAddress((void**)&p_m2, g_m2);
    cudaGetSymbolAddress((void**)&p_m3, g_m3);

    float* t[2]  = { p_t,  p_t  + (size_t)N_NODES * F0 };
    float* h[2]  = { p_h,  p_h  + (size_t)N_NODES * F0 };
    float* m1[2] = { p_m1, p_m1 + (size_t)N_NODES * 256 };
    float* m2[2] = { p_m2, p_m2 + (size_t)N_NODES * 128 };
    float* m3[2] = { p_m3, p_m3 + (size_t)N_NODES * 64 };

    const int TB = 256;
    const dim3 gN((N_NODES + TB - 1) / TB, 2);
    const dim3 gE((N_EDGES + TB - 1) / TB, 2);
    const int MB = (N_NODES + 127) / 128;   // 63

    init_kernel<<<gN, TB>>>();
    edge_kernel<<<gE, TB>>>(dmat[0], dmat[1], ei[0], ei[1]);
    scan_dinv_kernel<<<2, 1024>>>();

    // launch 4 (ncu capture slot): GCN layer-1 GEMM  t = x @ W1
    fp16_gemm<false, false, false><<<dim3(F0 / 128, MB, 2), 256>>>(
        x_in[0], x_in[1], W1[0], W1[1], nullptr, nullptr, t[0], t[1],
        N_NODES, F0, F0);

    scatter_coeff_kernel<<<gE, TB>>>(ei[0], ei[1]);

    aggregate_kernel<<<dim3(N_NODES, 2), 128>>>(t[0], t[1], b1[0], b1[1], h[0], h[1]);

    // GCN layer 2
    fp16_gemm<false, false, false><<<dim3(F0 / 128, MB, 2), 256>>>(
        h[0], h[1], W2[0], W2[1], nullptr, nullptr, t[0], t[1],
        N_NODES, F0, F0);
    aggregate_kernel<<<dim3(N_NODES, 2), 128>>>(t[0], t[1], b2[0], b2[1], h[0], h[1]);

    // MLP: L1 fp16 (512->256), L2/L3 fp32
    fp16_gemm<false, true, true><<<dim3(256 / 128, MB, 2), 256>>>(
        h[0], h[1], L1w[0], L1w[1], L1b[0], L1b[1], m1[0], m1[1],
        N_NODES, 256, F0);
    gemm_kernel<64, 64, 16, 4, 4, true, true>
        <<<dim3(2, (N_NODES + 63) / 64, 2), 256>>>(
            m1[0], m1[1], L2w[0], L2w[1], L2b[0], L2b[1], m2[0], m2[1],
            N_NODES, 128, 256);
    gemm_kernel<64, 64, 16, 4, 4, true, true>
        <<<dim3(1, (N_NODES + 63) / 64, 2), 256>>>(
            m2[0], m2[1], L3w[0], L3w[1], L3b[0], L3b[1], m3[0], m3[1],
            N_NODES, 64, 128);

    // final (fp16, TRANSB): out = x64_m @ y64_d^T  [8000 x 8000]
    fp16_gemm<true, false, false><<<dim3((N_NODES + 127) / 128, MB, 1), 256>>>(
        m3[0], m3[0], m3[1], m3[1], nullptr, nullptr, out, out,
        N_NODES, N_NODES, 64);
}

// round 11
// speedup vs baseline: 1.4024x; 1.0604x over previous
#include <cuda_runtime.h>
#include <cuda_fp16.h>
#include <math.h>

#define N_NODES 8000
#define N_EDGES 256000
#define F0      512

// ---------------- scratch (static device allocations; no cudaMalloc) --------
__device__ float g_w    [2][N_EDGES];
__device__ float g_dinv [2][N_NODES];
__device__ int   g_hist [2][N_NODES];
__device__ int   g_offs [2][N_NODES + 1];
__device__ int   g_fill [2][N_NODES];
__device__ int   g_crow [2][N_EDGES];
__device__ float g_ccoef[2][N_EDGES];
__device__ float g_t    [2][N_NODES * F0];
__device__ float g_h    [2][N_NODES * F0];
__device__ float g_m1   [2][N_NODES * 256];
__device__ float g_m2   [2][N_NODES * 128];
// fp16 operand copies
__device__ __half g_xh [2][N_NODES * F0];
__device__ __half g_hh [2][N_NODES * F0];
__device__ __half g_w1h[2][F0 * F0];
__device__ __half g_w2h[2][F0 * F0];
__device__ __half g_l1h[2][F0 * 256];
__device__ __half g_m3h[2][N_NODES * 64];

// ---------------- fp32 -> fp16 conversions -----------------------------------
__global__ void conv_x_kernel(const float* __restrict__ s0, const float* __restrict__ s1) {
    int i = (blockIdx.x * blockDim.x + threadIdx.x) * 4;
    int g = blockIdx.y;
    const float* s = g ? s1 : s0;
    if (i < N_NODES * F0) {
        float4 v = *reinterpret_cast<const float4*>(&s[i]);
        __half2 h0 = __floats2half2_rn(v.x, v.y);
        __half2 h1 = __floats2half2_rn(v.z, v.w);
        *reinterpret_cast<uint2*>(&g_xh[g][i]) =
            make_uint2(*reinterpret_cast<unsigned*>(&h0), *reinterpret_cast<unsigned*>(&h1));
    }
}

// z = 0:W1, 1:W2, 2:L1w
__global__ void conv_w_kernel(const float* __restrict__ w10, const float* __restrict__ w11,
                              const float* __restrict__ w20, const float* __restrict__ w21,
                              const float* __restrict__ l10, const float* __restrict__ l11) {
    int i = (blockIdx.x * blockDim.x + threadIdx.x) * 4;
    int g = blockIdx.y;
    int z = blockIdx.z;
    int n = (z == 2) ? F0 * 256 : F0 * F0;
    const float* s = (z == 0) ? (g ? w11 : w10) : (z == 1) ? (g ? w21 : w20) : (g ? l11 : l10);
    __half* d = (z == 0) ? g_w1h[g] : (z == 1) ? g_w2h[g] : g_l1h[g];
    if (i < n) {
        float4 v = *reinterpret_cast<const float4*>(&s[i]);
        __half2 h0 = __floats2half2_rn(v.x, v.y);
        __half2 h1 = __floats2half2_rn(v.z, v.w);
        *reinterpret_cast<uint2*>(&d[i]) =
            make_uint2(*reinterpret_cast<unsigned*>(&h0), *reinterpret_cast<unsigned*>(&h1));
    }
}

// ---------------- edge / degree prep (both graphs batched: blockIdx.y = g) --
__global__ void init_kernel() {
    int i = blockIdx.x * blockDim.x + threadIdx.x;
    int g = blockIdx.y;
    if (i < N_NODES) { g_dinv[g][i] = 1.0f; g_hist[g][i] = 0; }
}

__global__ void edge_kernel(const float* __restrict__ d0, const float* __restrict__ d1,
                            const int* __restrict__ e0, const int* __restrict__ e1) {
    int e = blockIdx.x * blockDim.x + threadIdx.x;
    int g = blockIdx.y;
    const float* data = g ? d1 : d0;
    const int*   ei   = g ? e1 : e0;
    if (e < N_EDGES) {
        int r = ei[e];
        int c = ei[N_EDGES + e];
        float v = fmaxf(data[(size_t)r * N_NODES + c], 0.0f);
        g_w[g][e] = v;
        atomicAdd(&g_dinv[g][c], v);
        atomicAdd(&g_hist[g][c], 1);
    }
}

__global__ void scan_dinv_kernel() {
    __shared__ int s[1024];
    int g = blockIdx.x;
    int t = threadIdx.x;
    for (int i = t; i < N_NODES; i += 1024)
        g_dinv[g][i] = rsqrtf(g_dinv[g][i]);
    int base = t * 8;
    int loc[8];
    int sum = 0;
#pragma unroll
    for (int j = 0; j < 8; j++) {
        int i = base + j;
        int v = (i < N_NODES) ? g_hist[g][i] : 0;
        loc[j] = sum;
        sum += v;
    }
    s[t] = sum;
    __syncthreads();
    for (int d = 1; d < 1024; d <<= 1) {
        int v = (t >= d) ? s[t - d] : 0;
        __syncthreads();
        s[t] += v;
        __syncthreads();
    }
    int cbase = s[t] - sum;
#pragma unroll
    for (int j = 0; j < 8; j++) {
        int i = base + j;
        if (i < N_NODES) {
            int o = cbase + loc[j];
            g_offs[g][i] = o;
            g_fill[g][i] = o;
        }
    }
    if (t == 0) g_offs[g][N_NODES] = N_EDGES;
}

__global__ void scatter_coeff_kernel(const int* __restrict__ e0, const int* __restrict__ e1) {
    int e = blockIdx.x * blockDim.x + threadIdx.x;
    int g = blockIdx.y;
    const int* ei = g ? e1 : e0;
    if (e < N_EDGES) {
        int r = ei[e];
        int c = ei[N_EDGES + e];
        float cf = g_dinv[g][r] * g_w[g][e] * g_dinv[g][c];
        int p = atomicAdd(&g_fill[g][c], 1);
        g_crow[g][p]  = r;
        g_ccoef[g][p] = cf;
    }
}

// ---------------- GCN aggregation (fp32 gather/accum; writes fp32 + fp16) ----
__global__ void aggregate_kernel(const float* __restrict__ t0, const float* __restrict__ t1,
                                 const float* __restrict__ bias0, const float* __restrict__ bias1,
                                 float* __restrict__ o0, float* __restrict__ o1) {
    int c = blockIdx.x;
    int g = blockIdx.y;
    const float* t    = g ? t1 : t0;
    const float* bias = g ? bias1 : bias0;
    float* out        = g ? o1 : o0;
    __half* outh      = g_hh[g];
    const int* __restrict__ crow = g_crow[g];
    const float* __restrict__ ccoef = g_ccoef[g];
    int f = threadIdx.x * 4;
    float dv = g_dinv[g][c];
    float sc = dv * dv;
    float4 v = *reinterpret_cast<const float4*>(&t[(size_t)c * F0 + f]);
    float4 acc = make_float4(v.x * sc, v.y * sc, v.z * sc, v.w * sc);
    int e0 = g_offs[g][c], e1 = g_offs[g][c + 1];
#pragma unroll 4
    for (int e = e0; e < e1; e++) {
        int   r  = crow[e];
        float cf = ccoef[e];
        float4 u = *reinterpret_cast<const float4*>(&t[(size_t)r * F0 + f]);
        acc.x += cf * u.x; acc.y += cf * u.y; acc.z += cf * u.z; acc.w += cf * u.w;
    }
    float4 b = *reinterpret_cast<const float4*>(&bias[f]);
    acc.x = fmaxf(acc.x + b.x, 0.0f);
    acc.y = fmaxf(acc.y + b.y, 0.0f);
    acc.z = fmaxf(acc.z + b.z, 0.0f);
    acc.w = fmaxf(acc.w + b.w, 0.0f);
    *reinterpret_cast<float4*>(&out[(size_t)c * F0 + f]) = acc;
    __half2 h0 = __floats2half2_rn(acc.x, acc.y);
    __half2 h1 = __floats2half2_rn(acc.z, acc.w);
    *reinterpret_cast<uint2*>(&outh[(size_t)c * F0 + f]) =
        make_uint2(*reinterpret_cast<unsigned*>(&h0), *reinterpret_cast<unsigned*>(&h1));
}

// ---------------- FP16 tensor-core GEMM (fp16-native + cp.async + ldmatrix) --
// 128x128x32 tile, 256 threads, 2-stage SMEM double buffer.
// C[Mn,Nn] = A[Mn,Kn] @ B  (B is [Kn,Nn] if !TRANSB else [Nn,Kn]); Kn % 32 == 0.
__device__ __forceinline__ void ldsm_x4(unsigned& r0, unsigned& r1,
                                        unsigned& r2, unsigned& r3, unsigned addr) {
    asm volatile("ldmatrix.sync.aligned.m8n8.x4.shared.b16 {%0,%1,%2,%3}, [%4];"
                 : "=r"(r0), "=r"(r1), "=r"(r2), "=r"(r3) : "r"(addr));
}
__device__ __forceinline__ void ldsm_x4_trans(unsigned& r0, unsigned& r1,
                                              unsigned& r2, unsigned& r3, unsigned addr) {
    asm volatile("ldmatrix.sync.aligned.m8n8.x4.trans.shared.b16 {%0,%1,%2,%3}, [%4];"
                 : "=r"(r0), "=r"(r1), "=r"(r2), "=r"(r3) : "r"(addr));
}
__device__ __forceinline__ void cpasync16(unsigned dst, const void* src) {
    asm volatile("cp.async.cg.shared.global [%0], [%1], 16;" :: "r"(dst), "l"(src));
}

template <bool TRANSB, bool BIAS, bool RELU>
__global__ __launch_bounds__(256)
void fp16_gemm(const __half* __restrict__ A0, const __half* __restrict__ A1,
               const __half* __restrict__ B0, const __half* __restrict__ B1,
               const float* __restrict__ bias0, const float* __restrict__ bias1,
               float* __restrict__ C0, float* __restrict__ C1,
               int Mn, int Nn, int Kn) {
    constexpr int BM = 128, BN = 128, BK = 32;
    constexpr int LDA  = BK / 2 + 4;  // 20 words = 80B rows (ldsm conflict-free)
    constexpr int LDB2 = BK / 2 + 4;  // TRANSB: same layout as A
    constexpr int LDBH = BN + 8;      // !TRANSB: [k][n] halfs, 272B rows
    constexpr int ASZ = BM * LDA;                                // words
    constexpr int BSZ = TRANSB ? (BN * LDB2) : (BK * LDBH / 2);  // words
    __shared__ unsigned As[2 * ASZ];
    __shared__ unsigned Bs[2 * BSZ];

    const int gsel = blockIdx.z;
    const __half* A   = gsel ? A1 : A0;
    const __half* B   = gsel ? B1 : B0;
    const float* bias = gsel ? bias1 : bias0;
    float*       C    = gsel ? C1 : C0;

    const int tid  = threadIdx.x;
    const int lane = tid & 31;
    const int wid  = tid >> 5;
    const int wm   = (wid & 1) * 64;
    const int wn   = (wid >> 1) * 32;
    const int q    = lane >> 2;
    const int r    = lane & 3;
    const int m0   = blockIdx.y * BM;
    const int n0   = blockIdx.x * BN;

    const int la_row  = ((lane >> 3) & 1) * 8 + (lane & 7);
    const int la_koff = ((lane >> 4) & 1) * 4;
    const int lbt_row = ((lane >> 4) & 1) * 8 + (lane & 7);
    const int lbt_koff= ((lane >> 3) & 1) * 4;
    const int lbn_k   = ((lane >> 3) & 1) * 8 + (lane & 7);
    const int lbn_n   = ((lane >> 4) & 1) * 8;

    const unsigned as_base = (unsigned)__cvta_generic_to_shared(As);
    const unsigned bs_base = (unsigned)__cvta_generic_to_shared(Bs);

    float c[4][4][4];
#pragma unroll
    for (int i = 0; i < 4; i++)
#pragma unroll
        for (int j = 0; j < 4; j++)
#pragma unroll
            for (int k = 0; k < 4; k++) c[i][j][k] = 0.0f;

    // cp.async staging: A tile 128 rows x 4 chunks(16B) = 512 tasks, 2/thread
    auto prefetchA = [&](int st, int k0) {
        unsigned dstb = as_base + st * ASZ * 4;
#pragma unroll
        for (int i = 0; i < 2; i++) {
            int p = tid + i * 256;
            int row = p >> 2;
            int ch  = p & 3;
            int gr = m0 + row; if (gr > Mn - 1) gr = Mn - 1;  // clamp (guarded at epilogue)
            cpasync16(dstb + (unsigned)(row * 80 + ch * 16),
                      A + (size_t)gr * Kn + k0 + ch * 8);
        }
    };
    auto prefetchB = [&](int st, int k0) {
        unsigned dstb = bs_base + st * BSZ * 4;
        if (!TRANSB) {
            // 32 k-rows x 16 chunks = 512 tasks (Nn % 128 == 0 on this path)
#pragma unroll
            for (int i = 0; i < 2; i++) {
                int p  = tid + i * 256;
                int kp = p >> 4;
                int ch = p & 15;
                cpasync16(dstb + (unsigned)(kp * 272 + ch * 16),
                          B + (size_t)(k0 + kp) * Nn + n0 + ch * 8);
            }
        } else {
            // 128 n-rows x 4 chunks = 512 tasks
#pragma unroll
            for (int i = 0; i < 2; i++) {
                int p = tid + i * 256;
                int row = p >> 2;
                int ch  = p & 3;
                int gn = n0 + row; if (gn > Nn - 1) gn = Nn - 1;
                cpasync16(dstb + (unsigned)(row * 80 + ch * 16),
                          B + (size_t)gn * Kn + k0 + ch * 8);
            }
        }
    };
    auto compute = [&](int st) {
        const unsigned a_st = as_base + st * ASZ * 4;
        const unsigned b_st = bs_base + st * BSZ * 4;
#pragma unroll
        for (int ks = 0; ks < BK / 2; ks += 8) {
            unsigned a[4][4], b[4][2];
#pragma unroll
            for (int tm = 0; tm < 4; tm++) {
                unsigned addr = a_st +
                    ((unsigned)((wm + tm * 16 + la_row) * LDA + ks + la_koff) << 2);
                ldsm_x4(a[tm][0], a[tm][1], a[tm][2], a[tm][3], addr);
            }
            if (!TRANSB) {
#pragma unroll
                for (int tp = 0; tp < 2; tp++) {
                    unsigned addr = b_st +
                        ((unsigned)((2 * ks + lbn_k) * LDBH + wn + tp * 16 + lbn_n) << 1);
                    ldsm_x4_trans(b[2 * tp][0], b[2 * tp][1],
                                  b[2 * tp + 1][0], b[2 * tp + 1][1], addr);
                }
            } else {
#pragma unroll
                for (int tp = 0; tp < 2; tp++) {
                    unsigned addr = b_st +
                        ((unsigned)((wn + tp * 16 + lbt_row) * LDB2 + ks + lbt_koff) << 2);
                    ldsm_x4(b[2 * tp][0], b[2 * tp][1],
                            b[2 * tp + 1][0], b[2 * tp + 1][1], addr);
                }
            }
#pragma unroll
            for (int tm = 0; tm < 4; tm++)
#pragma unroll
                for (int tn = 0; tn < 4; tn++) {
                    asm volatile(
                        "mma.sync.aligned.m16n8k16.row.col.f32.f16.f16.f32 "
                        "{%0,%1,%2,%3}, {%4,%5,%6,%7}, {%8,%9}, {%0,%1,%2,%3};"
                        : "+f"(c[tm][tn][0]), "+f"(c[tm][tn][1]),
                          "+f"(c[tm][tn][2]), "+f"(c[tm][tn][3])
                        : "r"(a[tm][0]), "r"(a[tm][1]), "r"(a[tm][2]), "r"(a[tm][3]),
                          "r"(b[tn][0]), "r"(b[tn][1]));
                }
        }
    };

    // prologue
    prefetchA(0, 0); prefetchB(0, 0);
    asm volatile("cp.async.commit_group;");

    int s = 0;
    for (int k0 = 0; k0 < Kn; k0 += BK, s ^= 1) {
        asm volatile("cp.async.wait_group 0;");
        __syncthreads();
        bool next = (k0 + BK) < Kn;
        if (next) {
            prefetchA(s ^ 1, k0 + BK);
            prefetchB(s ^ 1, k0 + BK);
            asm volatile("cp.async.commit_group;");
        }
        compute(s);
    }

    // epilogue
#pragma unroll
    for (int tm = 0; tm < 4; tm++) {
        int row = m0 + wm + tm * 16 + q;
#pragma unroll
        for (int tn = 0; tn < 4; tn++) {
            int col = n0 + wn + tn * 8 + 2 * r;
            if (col >= Nn) continue;
            float v0 = c[tm][tn][0], v1 = c[tm][tn][1];
            float v2 = c[tm][tn][2], v3 = c[tm][tn][3];
            if (BIAS) {
                float bb0 = bias[col], bb1 = bias[col + 1];
                v0 += bb0; v1 += bb1; v2 += bb0; v3 += bb1;
            }
            if (RELU) {
                v0 = fmaxf(v0, 0.f); v1 = fmaxf(v1, 0.f);
                v2 = fmaxf(v2, 0.f); v3 = fmaxf(v3, 0.f);
            }
            if (row < Mn)
                *reinterpret_cast<float2*>(&C[(size_t)row * Nn + col]) = make_float2(v0, v1);
            if (row + 8 < Mn)
                *reinterpret_cast<float2*>(&C[(size_t)(row + 8) * Nn + col]) = make_float2(v2, v3);
        }
    }
}

// ---------------- fp32 GEMM for narrow MLP layers (blockIdx.z = g) -----------
// HOUT: C pointers are __half* (fp16 output), else float*.
template <int BM, int BN, int BK, int TM, int TN, bool BIAS, bool RELU, bool HOUT>
__global__ __launch_bounds__((BM / TM) * (BN / TN))
void gemm_kernel(const float* __restrict__ A0, const float* __restrict__ A1,
                 const float* __restrict__ B0, const float* __restrict__ B1,
                 const float* __restrict__ bias0, const float* __restrict__ bias1,
                 void* __restrict__ C0v, void* __restrict__ C1v,
                 int Mn, int Nn, int Kn) {
    constexpr int THREADS = (BM / TM) * (BN / TN);
    __shared__ float As[BK][BM];
    __shared__ float Bs[BK][BN];
    const int gsel = blockIdx.z;
    const float* A    = gsel ? A1 : A0;
    const float* B    = gsel ? B1 : B0;
    const float* bias = gsel ? bias1 : bias0;
    void*        Cv   = gsel ? C1v : C0v;
    const int tid = threadIdx.x;
    const int tx = tid % (BN / TN);
    const int ty = tid / (BN / TN);
    const int m0 = blockIdx.y * BM;
    const int n0 = blockIdx.x * BN;

    float acc[TM][TN];
#pragma unroll
    for (int i = 0; i < TM; i++)
#pragma unroll
        for (int j = 0; j < TN; j++) acc[i][j] = 0.0f;

    for (int k0 = 0; k0 < Kn; k0 += BK) {
#pragma unroll
        for (int l = tid; l < BM * BK / 4; l += THREADS) {
            int row = l / (BK / 4);
            int kq  = (l % (BK / 4)) * 4;
            float4 v = make_float4(0.f, 0.f, 0.f, 0.f);
            if (m0 + row < Mn)
                v = *reinterpret_cast<const float4*>(&A[(size_t)(m0 + row) * Kn + k0 + kq]);
            As[kq + 0][row] = v.x; As[kq + 1][row] = v.y;
            As[kq + 2][row] = v.z; As[kq + 3][row] = v.w;
        }
#pragma unroll
        for (int l = tid; l < BK * BN / 4; l += THREADS) {
            int kk = l / (BN / 4);
            int nq = (l % (BN / 4)) * 4;
            float4 v = make_float4(0.f, 0.f, 0.f, 0.f);
            if (n0 + nq < Nn)
                v = *reinterpret_cast<const float4*>(&B[(size_t)(k0 + kk) * Nn + n0 + nq]);
            *reinterpret_cast<float4*>(&Bs[kk][nq]) = v;
        }
        __syncthreads();
#pragma unroll
        for (int k = 0; k < BK; k++) {
            float a[TM], b[TN];
#pragma unroll
            for (int i = 0; i < TM; i++) a[i] = As[k][ty * TM + i];
#pragma unroll
            for (int j = 0; j < TN; j++) b[j] = Bs[k][tx * TN + j];
#pragma unroll
            for (int i = 0; i < TM; i++)
#pragma unroll
                for (int j = 0; j < TN; j++) acc[i][j] += a[i] * b[j];
        }
        __syncthreads();
    }
#pragma unroll
    for (int i = 0; i < TM; i++) {
        int m = m0 + ty * TM + i;
        if (m >= Mn) continue;
#pragma unroll
        for (int j = 0; j < TN; j += 4) {
            int n = n0 + tx * TN + j;
            if (n >= Nn) continue;
            float4 v = make_float4(acc[i][j], acc[i][j + 1], acc[i][j + 2], acc[i][j + 3]);
            if (BIAS) {
                v.x += bias[n]; v.y += bias[n + 1]; v.z += bias[n + 2]; v.w += bias[n + 3];
            }
            if (RELU) {
                v.x = fmaxf(v.x, 0.f); v.y = fmaxf(v.y, 0.f);
                v.z = fmaxf(v.z, 0.f); v.w = fmaxf(v.w, 0.f);
            }
            if (HOUT) {
                __half* Ch = reinterpret_cast<__half*>(Cv);
                __half2 h0 = __floats2half2_rn(v.x, v.y);
                __half2 h1 = __floats2half2_rn(v.z, v.w);
                *reinterpret_cast<uint2*>(&Ch[(size_t)m * Nn + n]) =
                    make_uint2(*reinterpret_cast<unsigned*>(&h0),
                               *reinterpret_cast<unsigned*>(&h1));
            } else {
                *reinterpret_cast<float4*>(&reinterpret_cast<float*>(Cv)[(size_t)m * Nn + n]) = v;
            }
        }
    }
}

// ---------------- host-side orchestration -----------------------------------
extern "C" void kernel_launch(void* const* d_in, const int* in_sizes, int n_in,
                              void* d_out, int out_size) {
    const float* x_in[2]  = { (const float*)d_in[0], (const float*)d_in[1] };
    const float* dmat[2]  = { (const float*)d_in[2], (const float*)d_in[3] };
    const int*   ei[2]    = { (const int*)d_in[4],   (const int*)d_in[5]   };
    const float* W1[2]    = { (const float*)d_in[6],  (const float*)d_in[10] };
    const float* b1[2]    = { (const float*)d_in[7],  (const float*)d_in[11] };
    const float* W2[2]    = { (const float*)d_in[8],  (const float*)d_in[12] };
    const float* b2[2]    = { (const float*)d_in[9],  (const float*)d_in[13] };
    const float* L1w[2]   = { (const float*)d_in[14], (const float*)d_in[20] };
    const float* L1b[2]   = { (const float*)d_in[15], (const float*)d_in[21] };
    const float* L2w[2]   = { (const float*)d_in[16], (const float*)d_in[22] };
    const float* L2b[2]   = { (const float*)d_in[17], (const float*)d_in[23] };
    const float* L3w[2]   = { (const float*)d_in[18], (const float*)d_in[24] };
    const float* L3b[2]   = { (const float*)d_in[19], (const float*)d_in[25] };
    float* out = (float*)d_out;

    float *p_t, *p_h, *p_m1, *p_m2;
    __half *p_xh, *p_hh, *p_w1h, *p_w2h, *p_l1h, *p_m3h;
    cudaGetSymbolAddress((void**)&p_t,   g_t);
    cudaGetSymbolAddress((void**)&p_h,   g_h);
    cudaGetSymbolAddress((void**)&p_m1,  g_m1);
    cudaGetSymbolAddress((void**)&p_m2,  g_m2);
    cudaGetSymbolAddress((void**)&p_xh,  g_xh);
    cudaGetSymbolAddress((void**)&p_hh,  g_hh);
    cudaGetSymbolAddress((void**)&p_w1h, g_w1h);
    cudaGetSymbolAddress((void**)&p_w2h, g_w2h);
    cudaGetSymbolAddress((void**)&p_l1h, g_l1h);
    cudaGetSymbolAddress((void**)&p_m3h, g_m3h);

    float* t[2]  = { p_t,  p_t  + (size_t)N_NODES * F0 };
    float* h[2]  = { p_h,  p_h  + (size_t)N_NODES * F0 };
    float* m1[2] = { p_m1, p_m1 + (size_t)N_NODES * 256 };
    float* m2[2] = { p_m2, p_m2 + (size_t)N_NODES * 128 };
    __half* xh[2]  = { p_xh,  p_xh  + (size_t)N_NODES * F0 };
    __half* hh[2]  = { p_hh,  p_hh  + (size_t)N_NODES * F0 };
    __half* w1h[2] = { p_w1h, p_w1h + (size_t)F0 * F0 };
    __half* w2h[2] = { p_w2h, p_w2h + (size_t)F0 * F0 };
    __half* l1h[2] = { p_l1h, p_l1h + (size_t)F0 * 256 };
    __half* m3h[2] = { p_m3h, p_m3h + (size_t)N_NODES * 64 };

    const int TB = 256;
    const dim3 gN((N_NODES + TB - 1) / TB, 2);
    const dim3 gE((N_EDGES + TB - 1) / TB, 2);
    const int MB = (N_NODES + 127) / 128;   // 63

    // 1-3: conversions + init (GEMM1 deps first so ncu slot 4 = fp16_gemm)
    conv_x_kernel<<<dim3((N_NODES * F0 / 4 + TB - 1) / TB, 2), TB>>>(x_in[0], x_in[1]);
    conv_w_kernel<<<dim3((F0 * F0 / 4 + TB - 1) / TB, 2, 3), TB>>>(
        W1[0], W1[1], W2[0], W2[1], L1w[0], L1w[1]);
    init_kernel<<<gN, TB>>>();

    // 4 (ncu capture slot): GCN layer-1 GEMM  t = x @ W1
    fp16_gemm<false, false, false><<<dim3(F0 / 128, MB, 2), 256>>>(
        xh[0], xh[1], w1h[0], w1h[1], nullptr, nullptr, t[0], t[1],
        N_NODES, F0, F0);

    // finish edge prep
    edge_kernel<<<gE, TB>>>(dmat[0], dmat[1], ei[0], ei[1]);
    scan_dinv_kernel<<<2, 1024>>>();
    scatter_coeff_kernel<<<gE, TB>>>(ei[0], ei[1]);

    aggregate_kernel<<<dim3(N_NODES, 2), 128>>>(t[0], t[1], b1[0], b1[1], h[0], h[1]);

    // GCN layer 2 (A = hh fp16 from aggregate)
    fp16_gemm<false, false, false><<<dim3(F0 / 128, MB, 2), 256>>>(
        hh[0], hh[1], w2h[0], w2h[1], nullptr, nullptr, t[0], t[1],
        N_NODES, F0, F0);
    aggregate_kernel<<<dim3(N_NODES, 2), 128>>>(t[0], t[1], b2[0], b2[1], h[0], h[1]);

    // MLP: L1 fp16 (512->256), L2 fp32, L3 fp32 -> fp16 out
    fp16_gemm<false, true, true><<<dim3(256 / 128, MB, 2), 256>>>(
        hh[0], hh[1], l1h[0], l1h[1], L1b[0], L1b[1], m1[0], m1[1],
        N_NODES, 256, F0);
    gemm_kernel<64, 64, 16, 4, 4, true, true, false>
        <<<dim3(2, (N_NODES + 63) / 64, 2), 256>>>(
            m1[0], m1[1], L2w[0], L2w[1], L2b[0], L2b[1], m2[0], m2[1],
            N_NODES, 128, 256);
    gemm_kernel<64, 64, 16, 4, 4, true, true, true>
        <<<dim3(1, (N_NODES + 63) / 64, 2), 256>>>(
            m2[0], m2[1], L3w[0], L3w[1], L3b[0], L3b[1], m3h[0], m3h[1],
            N_NODES, 64, 128);

    // final (fp16, TRANSB): out = x64_m @ y64_d^T  [8000 x 8000]
    fp16_gemm<true, false, false><<<dim3((N_NODES + 127) / 128, MB, 1), 256>>>(
        m3h[0], m3h[0], m3h[1], m3h[1], nullptr, nullptr, out, out,
        N_NODES, N_NODES, 64);
}

// round 14
// speedup vs baseline: 1.4803x; 1.0555x over previous
#include <cuda_runtime.h>
#include <cuda_fp16.h>
#include <math.h>

#define N_NODES 8000
#define N_EDGES 256000
#define F0      512

// ---------------- scratch (static device allocations; no cudaMalloc) --------
__device__ float g_w    [2][N_EDGES];
__device__ float g_dinv [2][N_NODES];
__device__ int   g_hist [2][N_NODES];
__device__ int   g_offs [2][N_NODES + 1];
__device__ int   g_fill [2][N_NODES];
__device__ int   g_crow [2][N_EDGES];
__device__ float g_ccoef[2][N_EDGES];
__device__ float g_m1   [2][N_NODES * 256];
__device__ float g_m2   [2][N_NODES * 128];
// fp16 tensors (inter-stage dataflow is fp16)
__device__ __half g_xh [2][N_NODES * F0];
__device__ __half g_th [2][N_NODES * F0];   // GCN GEMM output (pre-aggregation)
__device__ __half g_hh [2][N_NODES * F0];   // aggregation output
__device__ __half g_w1h[2][F0 * F0];
__device__ __half g_w2h[2][F0 * F0];
__device__ __half g_l1h[2][F0 * 256];
__device__ __half g_m3h[2][N_NODES * 64];

// ---------------- fp32 -> fp16 conversions -----------------------------------
__global__ void conv_x_kernel(const float* __restrict__ s0, const float* __restrict__ s1) {
    int i = (blockIdx.x * blockDim.x + threadIdx.x) * 4;
    int g = blockIdx.y;
    const float* s = g ? s1 : s0;
    if (i < N_NODES * F0) {
        float4 v = *reinterpret_cast<const float4*>(&s[i]);
        __half2 h0 = __floats2half2_rn(v.x, v.y);
        __half2 h1 = __floats2half2_rn(v.z, v.w);
        *reinterpret_cast<uint2*>(&g_xh[g][i]) =
            make_uint2(*reinterpret_cast<unsigned*>(&h0), *reinterpret_cast<unsigned*>(&h1));
    }
}

// z = 0:W1, 1:W2, 2:L1w   (kept [K][N] layout, fp16)
__global__ void conv_w_kernel(const float* __restrict__ w10, const float* __restrict__ w11,
                              const float* __restrict__ w20, const float* __restrict__ w21,
                              const float* __restrict__ l10, const float* __restrict__ l11) {
    int i = (blockIdx.x * blockDim.x + threadIdx.x) * 4;
    int g = blockIdx.y;
    int z = blockIdx.z;
    int n = (z == 2) ? F0 * 256 : F0 * F0;
    const float* s = (z == 0) ? (g ? w11 : w10) : (z == 1) ? (g ? w21 : w20) : (g ? l11 : l10);
    __half* d = (z == 0) ? g_w1h[g] : (z == 1) ? g_w2h[g] : g_l1h[g];
    if (i < n) {
        float4 v = *reinterpret_cast<const float4*>(&s[i]);
        __half2 h0 = __floats2half2_rn(v.x, v.y);
        __half2 h1 = __floats2half2_rn(v.z, v.w);
        *reinterpret_cast<uint2*>(&d[i]) =
            make_uint2(*reinterpret_cast<unsigned*>(&h0), *reinterpret_cast<unsigned*>(&h1));
    }
}

// ---------------- edge / degree prep (both graphs batched: blockIdx.y = g) --
__global__ void init_kernel() {
    int i = blockIdx.x * blockDim.x + threadIdx.x;
    int g = blockIdx.y;
    if (i < N_NODES) { g_dinv[g][i] = 1.0f; g_hist[g][i] = 0; }
}

__global__ void edge_kernel(const float* __restrict__ d0, const float* __restrict__ d1,
                            const int* __restrict__ e0, const int* __restrict__ e1) {
    int e = blockIdx.x * blockDim.x + threadIdx.x;
    int g = blockIdx.y;
    const float* data = g ? d1 : d0;
    const int*   ei   = g ? e1 : e0;
    if (e < N_EDGES) {
        int r = ei[e];
        int c = ei[N_EDGES + e];
        float v = fmaxf(data[(size_t)r * N_NODES + c], 0.0f);
        g_w[g][e] = v;
        atomicAdd(&g_dinv[g][c], v);
        atomicAdd(&g_hist[g][c], 1);
    }
}

__global__ void scan_dinv_kernel() {
    __shared__ int s[1024];
    int g = blockIdx.x;
    int t = threadIdx.x;
    for (int i = t; i < N_NODES; i += 1024)
        g_dinv[g][i] = rsqrtf(g_dinv[g][i]);
    int base = t * 8;
    int loc[8];
    int sum = 0;
#pragma unroll
    for (int j = 0; j < 8; j++) {
        int i = base + j;
        int v = (i < N_NODES) ? g_hist[g][i] : 0;
        loc[j] = sum;
        sum += v;
    }
    s[t] = sum;
    __syncthreads();
    for (int d = 1; d < 1024; d <<= 1) {
        int v = (t >= d) ? s[t - d] : 0;
        __syncthreads();
        s[t] += v;
        __syncthreads();
    }
    int cbase = s[t] - sum;
#pragma unroll
    for (int j = 0; j < 8; j++) {
        int i = base + j;
        if (i < N_NODES) {
            int o = cbase + loc[j];
            g_offs[g][i] = o;
            g_fill[g][i] = o;
        }
    }
    if (t == 0) g_offs[g][N_NODES] = N_EDGES;
}

__global__ void scatter_coeff_kernel(const int* __restrict__ e0, const int* __restrict__ e1) {
    int e = blockIdx.x * blockDim.x + threadIdx.x;
    int g = blockIdx.y;
    const int* ei = g ? e1 : e0;
    if (e < N_EDGES) {
        int r = ei[e];
        int c = ei[N_EDGES + e];
        float cf = g_dinv[g][r] * g_w[g][e] * g_dinv[g][c];
        int p = atomicAdd(&g_fill[g][c], 1);
        g_crow[g][p]  = r;
        g_ccoef[g][p] = cf;
    }
}

// ---------------- GCN aggregation (fp16 gather, fp32 accum, fp16 out) --------
__global__ void aggregate_kernel(const float* __restrict__ bias0,
                                 const float* __restrict__ bias1) {
    int c = blockIdx.x;
    int g = blockIdx.y;
    const float* bias = g ? bias1 : bias0;
    const __half* __restrict__ th = g_th[g];
    __half* outh = g_hh[g];
    const int* __restrict__ crow = g_crow[g];
    const float* __restrict__ ccoef = g_ccoef[g];
    int f = threadIdx.x * 4;
    float dv = g_dinv[g][c];
    float sc = dv * dv;
    uint2 sraw = *reinterpret_cast<const uint2*>(&th[(size_t)c * F0 + f]);
    float2 s0 = __half22float2(*reinterpret_cast<__half2*>(&sraw.x));
    float2 s1 = __half22float2(*reinterpret_cast<__half2*>(&sraw.y));
    float4 acc = make_float4(s0.x * sc, s0.y * sc, s1.x * sc, s1.y * sc);
    int e0 = g_offs[g][c], e1 = g_offs[g][c + 1];
#pragma unroll 4
    for (int e = e0; e < e1; e++) {
        int   r  = crow[e];
        float cf = ccoef[e];
        uint2 raw = *reinterpret_cast<const uint2*>(&th[(size_t)r * F0 + f]);
        float2 u0 = __half22float2(*reinterpret_cast<__half2*>(&raw.x));
        float2 u1 = __half22float2(*reinterpret_cast<__half2*>(&raw.y));
        acc.x += cf * u0.x; acc.y += cf * u0.y;
        acc.z += cf * u1.x; acc.w += cf * u1.y;
    }
    float4 b = *reinterpret_cast<const float4*>(&bias[f]);
    acc.x = fmaxf(acc.x + b.x, 0.0f);
    acc.y = fmaxf(acc.y + b.y, 0.0f);
    acc.z = fmaxf(acc.z + b.z, 0.0f);
    acc.w = fmaxf(acc.w + b.w, 0.0f);
    __half2 h0 = __floats2half2_rn(acc.x, acc.y);
    __half2 h1 = __floats2half2_rn(acc.z, acc.w);
    *reinterpret_cast<uint2*>(&outh[(size_t)c * F0 + f]) =
        make_uint2(*reinterpret_cast<unsigned*>(&h0), *reinterpret_cast<unsigned*>(&h1));
}

// ---------------- FP16 tensor-core GEMM (fp16-native + cp.async + ldmatrix) --
// 128x128x32 tile, 256 threads, 2-stage SMEM double buffer, batched frag loads.
// C[Mn,Nn] = A[Mn,Kn] @ B  (B is [Kn,Nn] if !TRANSB else [Nn,Kn]); Kn % 32 == 0.
// OUTM: 0 = fp32 C, 1 = fp16 C.
__device__ __forceinline__ void ldsm_x4(unsigned& r0, unsigned& r1,
                                        unsigned& r2, unsigned& r3, unsigned addr) {
    asm volatile("ldmatrix.sync.aligned.m8n8.x4.shared.b16 {%0,%1,%2,%3}, [%4];"
                 : "=r"(r0), "=r"(r1), "=r"(r2), "=r"(r3) : "r"(addr));
}
__device__ __forceinline__ void ldsm_x4_trans(unsigned& r0, unsigned& r1,
                                              unsigned& r2, unsigned& r3, unsigned addr) {
    asm volatile("ldmatrix.sync.aligned.m8n8.x4.trans.shared.b16 {%0,%1,%2,%3}, [%4];"
                 : "=r"(r0), "=r"(r1), "=r"(r2), "=r"(r3) : "r"(addr));
}
__device__ __forceinline__ void cpasync16(unsigned dst, const void* src) {
    asm volatile("cp.async.cg.shared.global [%0], [%1], 16;" :: "r"(dst), "l"(src));
}

template <bool TRANSB, bool BIAS, bool RELU, int OUTM>
__global__ __launch_bounds__(256, 2)
void fp16_gemm(const __half* __restrict__ A0, const __half* __restrict__ A1,
               const __half* __restrict__ B0, const __half* __restrict__ B1,
               const float* __restrict__ bias0, const float* __restrict__ bias1,
               void* __restrict__ C0v, void* __restrict__ C1v,
               int Mn, int Nn, int Kn) {
    constexpr int BM = 128, BN = 128, BK = 32;
    constexpr int LDA  = BK / 2 + 4;  // 20 words = 80B rows (ldsm conflict-free)
    constexpr int LDB2 = BK / 2 + 4;  // TRANSB: same layout as A
    constexpr int LDBH = BN + 8;      // !TRANSB: [k][n] halfs, 272B rows
    constexpr int ASZ = BM * LDA;                                // words
    constexpr int BSZ = TRANSB ? (BN * LDB2) : (BK * LDBH / 2);  // words
    __shared__ unsigned As[2 * ASZ];
    __shared__ unsigned Bs[2 * BSZ];

    const int gsel = blockIdx.z;
    const __half* A   = gsel ? A1 : A0;
    const __half* B   = gsel ? B1 : B0;
    const float* bias = gsel ? bias1 : bias0;
    void*        Cv   = gsel ? C1v : C0v;

    const int tid  = threadIdx.x;
    const int lane = tid & 31;
    const int wid  = tid >> 5;
    const int wm   = (wid & 1) * 64;
    const int wn   = (wid >> 1) * 32;
    const int q    = lane >> 2;
    const int r    = lane & 3;
    const int m0   = blockIdx.y * BM;
    const int n0   = blockIdx.x * BN;

    const int la_row  = ((lane >> 3) & 1) * 8 + (lane & 7);
    const int la_koff = ((lane >> 4) & 1) * 4;
    const int lbt_row = ((lane >> 4) & 1) * 8 + (lane & 7);
    const int lbt_koff= ((lane >> 3) & 1) * 4;
    const int lbn_k   = ((lane >> 3) & 1) * 8 + (lane & 7);
    const int lbn_n   = ((lane >> 4) & 1) * 8;

    const unsigned as_base = (unsigned)__cvta_generic_to_shared(As);
    const unsigned bs_base = (unsigned)__cvta_generic_to_shared(Bs);

    float c[4][4][4];
#pragma unroll
    for (int i = 0; i < 4; i++)
#pragma unroll
        for (int j = 0; j < 4; j++)
#pragma unroll
            for (int k = 0; k < 4; k++) c[i][j][k] = 0.0f;

    auto prefetchA = [&](int st, int k0) {
        unsigned dstb = as_base + st * ASZ * 4;
#pragma unroll
        for (int i = 0; i < 2; i++) {
            int p = tid + i * 256;
            int row = p >> 2;
            int ch  = p & 3;
            int gr = m0 + row; if (gr > Mn - 1) gr = Mn - 1;
            cpasync16(dstb + (unsigned)(row * 80 + ch * 16),
                      A + (size_t)gr * Kn + k0 + ch * 8);
        }
    };
    auto prefetchB = [&](int st, int k0) {
        unsigned dstb = bs_base + st * BSZ * 4;
        if (!TRANSB) {
#pragma unroll
            for (int i = 0; i < 2; i++) {
                int p  = tid + i * 256;
                int kp = p >> 4;
                int ch = p & 15;
                cpasync16(dstb + (unsigned)(kp * 272 + ch * 16),
                          B + (size_t)(k0 + kp) * Nn + n0 + ch * 8);
            }
        } else {
#pragma unroll
            for (int i = 0; i < 2; i++) {
                int p = tid + i * 256;
                int row = p >> 2;
                int ch  = p & 3;
                int gn = n0 + row; if (gn > Nn - 1) gn = Nn - 1;
                cpasync16(dstb + (unsigned)(row * 80 + ch * 16),
                          B + (size_t)gn * Kn + k0 + ch * 8);
            }
        }
    };
    auto compute = [&](int st) {
        const unsigned a_st = as_base + st * ASZ * 4;
        const unsigned b_st = bs_base + st * BSZ * 4;
        unsigned a[2][4][4], b[2][4][2];
        // batched fragment loads for BOTH k-steps, then all MMAs
#pragma unroll
        for (int hh = 0; hh < 2; hh++) {
            int ks = hh * 8;
#pragma unroll
            for (int tm = 0; tm < 4; tm++) {
                unsigned addr = a_st +
                    ((unsigned)((wm + tm * 16 + la_row) * LDA + ks + la_koff) << 2);
                ldsm_x4(a[hh][tm][0], a[hh][tm][1], a[hh][tm][2], a[hh][tm][3], addr);
            }
            if (!TRANSB) {
#pragma unroll
                for (int tp = 0; tp < 2; tp++) {
                    unsigned addr = b_st +
                        ((unsigned)((2 * ks + lbn_k) * LDBH + wn + tp * 16 + lbn_n) << 1);
                    ldsm_x4_trans(b[hh][2 * tp][0], b[hh][2 * tp][1],
                                  b[hh][2 * tp + 1][0], b[hh][2 * tp + 1][1], addr);
                }
            } else {
#pragma unroll
                for (int tp = 0; tp < 2; tp++) {
                    unsigned addr = b_st +
                        ((unsigned)((wn + tp * 16 + lbt_row) * LDB2 + ks + lbt_koff) << 2);
                    ldsm_x4(b[hh][2 * tp][0], b[hh][2 * tp][1],
                            b[hh][2 * tp + 1][0], b[hh][2 * tp + 1][1], addr);
                }
            }
        }
#pragma unroll
        for (int hh = 0; hh < 2; hh++)
#pragma unroll
            for (int tm = 0; tm < 4; tm++)
#pragma unroll
                for (int tn = 0; tn < 4; tn++) {
                    asm volatile(
                        "mma.sync.aligned.m16n8k16.row.col.f32.f16.f16.f32 "
                        "{%0,%1,%2,%3}, {%4,%5,%6,%7}, {%8,%9}, {%0,%1,%2,%3};"
                        : "+f"(c[tm][tn][0]), "+f"(c[tm][tn][1]),
                          "+f"(c[tm][tn][2]), "+f"(c[tm][tn][3])
                        : "r"(a[hh][tm][0]), "r"(a[hh][tm][1]),
                          "r"(a[hh][tm][2]), "r"(a[hh][tm][3]),
                          "r"(b[hh][tn][0]), "r"(b[hh][tn][1]));
                }
    };

    prefetchA(0, 0);
    prefetchB(0, 0);
    asm volatile("cp.async.commit_group;");

    int s = 0;
    for (int k0 = 0; k0 < Kn; k0 += BK, s ^= 1) {
        asm volatile("cp.async.wait_group 0;");
        __syncthreads();
        bool next = (k0 + BK) < Kn;
        if (next) {
            prefetchA(s ^ 1, k0 + BK);
            prefetchB(s ^ 1, k0 + BK);
            asm volatile("cp.async.commit_group;");
        }
        compute(s);
    }

    // epilogue
#pragma unroll
    for (int tm = 0; tm < 4; tm++) {
        int row = m0 + wm + tm * 16 + q;
#pragma unroll
        for (int tn = 0; tn < 4; tn++) {
            int col = n0 + wn + tn * 8 + 2 * r;
            if (col >= Nn) continue;
            float v0 = c[tm][tn][0], v1 = c[tm][tn][1];
            float v2 = c[tm][tn][2], v3 = c[tm][tn][3];
            if (BIAS) {
                float bb0 = bias[col], bb1 = bias[col + 1];
                v0 += bb0; v1 += bb1; v2 += bb0; v3 += bb1;
            }
            if (RELU) {
                v0 = fmaxf(v0, 0.f); v1 = fmaxf(v1, 0.f);
                v2 = fmaxf(v2, 0.f); v3 = fmaxf(v3, 0.f);
            }
            if (OUTM == 0) {
                float* Cf = reinterpret_cast<float*>(Cv);
                if (row < Mn)
                    *reinterpret_cast<float2*>(&Cf[(size_t)row * Nn + col]) = make_float2(v0, v1);
                if (row + 8 < Mn)
                    *reinterpret_cast<float2*>(&Cf[(size_t)(row + 8) * Nn + col]) = make_float2(v2, v3);
            } else {
                __half* Ch = reinterpret_cast<__half*>(Cv);
                if (row < Mn) {
                    __half2 p = __floats2half2_rn(v0, v1);
                    *reinterpret_cast<unsigned*>(&Ch[(size_t)row * Nn + col]) =
                        *reinterpret_cast<unsigned*>(&p);
                }
                if (row + 8 < Mn) {
                    __half2 p = __floats2half2_rn(v2, v3);
                    *reinterpret_cast<unsigned*>(&Ch[(size_t)(row + 8) * Nn + col]) =
                        *reinterpret_cast<unsigned*>(&p);
                }
            }
        }
    }
}

// ---------------- fp32 GEMM for narrow MLP layers (blockIdx.z = g) -----------
template <int BM, int BN, int BK, int TM, int TN, bool BIAS, bool RELU, bool HOUT>
__global__ __launch_bounds__((BM / TM) * (BN / TN))
void gemm_kernel(const float* __restrict__ A0, const float* __restrict__ A1,
                 const float* __restrict__ B0, const float* __restrict__ B1,
                 const float* __restrict__ bias0, const float* __restrict__ bias1,
                 void* __restrict__ C0v, void* __restrict__ C1v,
                 int Mn, int Nn, int Kn) {
    constexpr int THREADS = (BM / TM) * (BN / TN);
    __shared__ float As[BK][BM];
    __shared__ float Bs[BK][BN];
    const int gsel = blockIdx.z;
    const float* A    = gsel ? A1 : A0;
    const float* B    = gsel ? B1 : B0;
    const float* bias = gsel ? bias1 : bias0;
    void*        Cv   = gsel ? C1v : C0v;
    const int tid = threadIdx.x;
    const int tx = tid % (BN / TN);
    const int ty = tid / (BN / TN);
    const int m0 = blockIdx.y * BM;
    const int n0 = blockIdx.x * BN;

    float acc[TM][TN];
#pragma unroll
    for (int i = 0; i < TM; i++)
#pragma unroll
        for (int j = 0; j < TN; j++) acc[i][j] = 0.0f;

    for (int k0 = 0; k0 < Kn; k0 += BK) {
#pragma unroll
        for (int l = tid; l < BM * BK / 4; l += THREADS) {
            int row = l / (BK / 4);
            int kq  = (l % (BK / 4)) * 4;
            float4 v = make_float4(0.f, 0.f, 0.f, 0.f);
            if (m0 + row < Mn)
                v = *reinterpret_cast<const float4*>(&A[(size_t)(m0 + row) * Kn + k0 + kq]);
            As[kq + 0][row] = v.x; As[kq + 1][row] = v.y;
            As[kq + 2][row] = v.z; As[kq + 3][row] = v.w;
        }
#pragma unroll
        for (int l = tid; l < BK * BN / 4; l += THREADS) {
            int kk = l / (BN / 4);
            int nq = (l % (BN / 4)) * 4;
            float4 v = make_float4(0.f, 0.f, 0.f, 0.f);
            if (n0 + nq < Nn)
                v = *reinterpret_cast<const float4*>(&B[(size_t)(k0 + kk) * Nn + n0 + nq]);
            *reinterpret_cast<float4*>(&Bs[kk][nq]) = v;
        }
        __syncthreads();
#pragma unroll
        for (int k = 0; k < BK; k++) {
            float a[TM], b[TN];
#pragma unroll
            for (int i = 0; i < TM; i++) a[i] = As[k][ty * TM + i];
#pragma unroll
            for (int j = 0; j < TN; j++) b[j] = Bs[k][tx * TN + j];
#pragma unroll
            for (int i = 0; i < TM; i++)
#pragma unroll
                for (int j = 0; j < TN; j++) acc[i][j] += a[i] * b[j];
        }
        __syncthreads();
    }
#pragma unroll
    for (int i = 0; i < TM; i++) {
        int m = m0 + ty * TM + i;
        if (m >= Mn) continue;
#pragma unroll
        for (int j = 0; j < TN; j += 4) {
            int n = n0 + tx * TN + j;
            if (n >= Nn) continue;
            float4 v = make_float4(acc[i][j], acc[i][j + 1], acc[i][j + 2], acc[i][j + 3]);
            if (BIAS) {
                v.x += bias[n]; v.y += bias[n + 1]; v.z += bias[n + 2]; v.w += bias[n + 3];
            }
            if (RELU) {
                v.x = fmaxf(v.x, 0.f); v.y = fmaxf(v.y, 0.f);
                v.z = fmaxf(v.z, 0.f); v.w = fmaxf(v.w, 0.f);
            }
            if (HOUT) {
                __half* Ch = reinterpret_cast<__half*>(Cv);
                __half2 h0 = __floats2half2_rn(v.x, v.y);
                __half2 h1 = __floats2half2_rn(v.z, v.w);
                *reinterpret_cast<uint2*>(&Ch[(size_t)m * Nn + n]) =
                    make_uint2(*reinterpret_cast<unsigned*>(&h0),
                               *reinterpret_cast<unsigned*>(&h1));
            } else {
                *reinterpret_cast<float4*>(&reinterpret_cast<float*>(Cv)[(size_t)m * Nn + n]) = v;
            }
        }
    }
}

// ---------------- host-side orchestration -----------------------------------
extern "C" void kernel_launch(void* const* d_in, const int* in_sizes, int n_in,
                              void* d_out, int out_size) {
    const float* x_in[2]  = { (const float*)d_in[0], (const float*)d_in[1] };
    const float* dmat[2]  = { (const float*)d_in[2], (const float*)d_in[3] };
    const int*   ei[2]    = { (const int*)d_in[4],   (const int*)d_in[5]   };
    const float* W1[2]    = { (const float*)d_in[6],  (const float*)d_in[10] };
    const float* b1[2]    = { (const float*)d_in[7],  (const float*)d_in[11] };
    const float* W2[2]    = { (const float*)d_in[8],  (const float*)d_in[12] };
    const float* b2[2]    = { (const float*)d_in[9],  (const float*)d_in[13] };
    const float* L1w[2]   = { (const float*)d_in[14], (const float*)d_in[20] };
    const float* L1b[2]   = { (const float*)d_in[15], (const float*)d_in[21] };
    const float* L2w[2]   = { (const float*)d_in[16], (const float*)d_in[22] };
    const float* L2b[2]   = { (const float*)d_in[17], (const float*)d_in[23] };
    const float* L3w[2]   = { (const float*)d_in[18], (const float*)d_in[24] };
    const float* L3b[2]   = { (const float*)d_in[19], (const float*)d_in[25] };
    float* out = (float*)d_out;

    float *p_m1, *p_m2;
    __half *p_xh, *p_th, *p_hh, *p_w1h, *p_w2h, *p_l1h, *p_m3h;
    cudaGetSymbolAddress((void**)&p_m1,  g_m1);
    cudaGetSymbolAddress((void**)&p_m2,  g_m2);
    cudaGetSymbolAddress((void**)&p_xh,  g_xh);
    cudaGetSymbolAddress((void**)&p_th,  g_th);
    cudaGetSymbolAddress((void**)&p_hh,  g_hh);
    cudaGetSymbolAddress((void**)&p_w1h, g_w1h);
    cudaGetSymbolAddress((void**)&p_w2h, g_w2h);
    cudaGetSymbolAddress((void**)&p_l1h, g_l1h);
    cudaGetSymbolAddress((void**)&p_m3h, g_m3h);

    float* m1[2] = { p_m1, p_m1 + (size_t)N_NODES * 256 };
    float* m2[2] = { p_m2, p_m2 + (size_t)N_NODES * 128 };
    __half* xh[2]  = { p_xh,  p_xh  + (size_t)N_NODES * F0 };
    __half* th[2]  = { p_th,  p_th  + (size_t)N_NODES * F0 };
    __half* hh[2]  = { p_hh,  p_hh  + (size_t)N_NODES * F0 };
    __half* w1h[2] = { p_w1h, p_w1h + (size_t)F0 * F0 };
    __half* w2h[2] = { p_w2h, p_w2h + (size_t)F0 * F0 };
    __half* l1h[2] = { p_l1h, p_l1h + (size_t)F0 * 256 };
    __half* m3h[2] = { p_m3h, p_m3h + (size_t)N_NODES * 64 };

    const int TB = 256;
    const dim3 gN((N_NODES + TB - 1) / TB, 2);
    const dim3 gE((N_EDGES + TB - 1) / TB, 2);
    const int MB = (N_NODES + 127) / 128;   // 63

    // 1-3: conversions + init (GEMM1 deps first so ncu slot 4 = fp16_gemm)
    conv_x_kernel<<<dim3((N_NODES * F0 / 4 + TB - 1) / TB, 2), TB>>>(x_in[0], x_in[1]);
    conv_w_kernel<<<dim3((F0 * F0 / 4 + TB - 1) / TB, 2, 3), TB>>>(
        W1[0], W1[1], W2[0], W2[1], L1w[0], L1w[1]);
    init_kernel<<<gN, TB>>>();

    // 4 (ncu capture slot): GCN layer-1 GEMM  th = fp16(x @ W1)
    fp16_gemm<false, false, false, 1><<<dim3(F0 / 128, MB, 2), 256>>>(
        xh[0], xh[1], w1h[0], w1h[1], nullptr, nullptr, th[0], th[1],
        N_NODES, F0, F0);

    // finish edge prep
    edge_kernel<<<gE, TB>>>(dmat[0], dmat[1], ei[0], ei[1]);
    scan_dinv_kernel<<<2, 1024>>>();
    scatter_coeff_kernel<<<gE, TB>>>(ei[0], ei[1]);

    // agg1: hh = fp16(relu(agg(th) + b1))
    aggregate_kernel<<<dim3(N_NODES, 2), 128>>>(b1[0], b1[1]);

    // GCN layer 2
    fp16_gemm<false, false, false, 1><<<dim3(F0 / 128, MB, 2), 256>>>(
        hh[0], hh[1], w2h[0], w2h[1], nullptr, nullptr, th[0], th[1],
        N_NODES, F0, F0);
    aggregate_kernel<<<dim3(N_NODES, 2), 128>>>(b2[0], b2[1]);

    // MLP: L1 fp16 (512->256, fp32 out), L2 fp32, L3 fp32 -> fp16 out
    fp16_gemm<false, true, true, 0><<<dim3(256 / 128, MB, 2), 256>>>(
        hh[0], hh[1], l1h[0], l1h[1], L1b[0], L1b[1], m1[0], m1[1],
        N_NODES, 256, F0);
    gemm_kernel<64, 64, 16, 4, 4, true, true, false>
        <<<dim3(2, (N_NODES + 63) / 64, 2), 256>>>(
            m1[0], m1[1], L2w[0], L2w[1], L2b[0], L2b[1], m2[0], m2[1],
            N_NODES, 128, 256);
    gemm_kernel<64, 64, 16, 4, 4, true, true, true>
        <<<dim3(1, (N_NODES + 63) / 64, 2), 256>>>(
            m2[0], m2[1], L3w[0], L3w[1], L3b[0], L3b[1], m3h[0], m3h[1],
            N_NODES, 64, 128);

    // final (fp16, TRANSB): out = x64_m @ y64_d^T  [8000 x 8000]
    fp16_gemm<true, false, false, 0><<<dim3((N_NODES + 127) / 128, MB, 1), 256>>>(
        m3h[0], m3h[0], m3h[1], m3h[1], nullptr, nullptr, out, out,
        N_NODES, N_NODES, 64);
}

// round 15
// speedup vs baseline: 1.6671x; 1.1262x over previous
#include <cuda_runtime.h>
#include <cuda_fp16.h>
#include <math.h>

#define N_NODES 8000
#define N_EDGES 256000
#define F0      512

// ---------------- scratch (static device allocations; no cudaMalloc) --------
__device__ float g_w    [2][N_EDGES];
__device__ float g_dinv [2][N_NODES];
__device__ int   g_hist [2][N_NODES];
__device__ int   g_offs [2][N_NODES + 1];
__device__ int   g_fill [2][N_NODES];
__device__ int   g_crow [2][N_EDGES];
__device__ float g_ccoef[2][N_EDGES];
// fp16 tensors (whole dataflow is fp16)
__device__ __half g_xh [2][N_NODES * F0];
__device__ __half g_th [2][N_NODES * F0];   // GCN GEMM output (pre-aggregation)
__device__ __half g_hh [2][N_NODES * F0];   // aggregation output
__device__ __half g_w1h[2][F0 * F0];
__device__ __half g_w2h[2][F0 * F0];
__device__ __half g_l1h[2][F0 * 256];
__device__ __half g_l2h[2][256 * 128];
__device__ __half g_l3h[2][128 * 64 + 64];  // +64 pad: B prefetch reads 128 cols
__device__ __half g_m1h[2][N_NODES * 256];
__device__ __half g_m2h[2][N_NODES * 128];
__device__ __half g_m3h[2][N_NODES * 64];

// ---------------- fp32 -> fp16 conversions -----------------------------------
__global__ void conv_x_kernel(const float* __restrict__ s0, const float* __restrict__ s1) {
    int i = (blockIdx.x * blockDim.x + threadIdx.x) * 4;
    int g = blockIdx.y;
    const float* s = g ? s1 : s0;
    if (i < N_NODES * F0) {
        float4 v = *reinterpret_cast<const float4*>(&s[i]);
        __half2 h0 = __floats2half2_rn(v.x, v.y);
        __half2 h1 = __floats2half2_rn(v.z, v.w);
        *reinterpret_cast<uint2*>(&g_xh[g][i]) =
            make_uint2(*reinterpret_cast<unsigned*>(&h0), *reinterpret_cast<unsigned*>(&h1));
    }
}

// z = 0:W1, 1:W2, 2:L1w, 3:L2w, 4:L3w   (kept [K][N] layout, fp16)
__global__ void conv_w_kernel(const float* __restrict__ w10, const float* __restrict__ w11,
                              const float* __restrict__ w20, const float* __restrict__ w21,
                              const float* __restrict__ l10, const float* __restrict__ l11,
                              const float* __restrict__ l20, const float* __restrict__ l21,
                              const float* __restrict__ l30, const float* __restrict__ l31) {
    int i = (blockIdx.x * blockDim.x + threadIdx.x) * 4;
    int g = blockIdx.y;
    int z = blockIdx.z;
    int n = (z <= 1) ? F0 * F0 : (z == 2) ? F0 * 256 : (z == 3) ? 256 * 128 : 128 * 64;
    const float* s =
        (z == 0) ? (g ? w11 : w10) : (z == 1) ? (g ? w21 : w20) :
        (z == 2) ? (g ? l11 : l10) : (z == 3) ? (g ? l21 : l20) : (g ? l31 : l30);
    __half* d = (z == 0) ? g_w1h[g] : (z == 1) ? g_w2h[g] :
                (z == 2) ? g_l1h[g] : (z == 3) ? g_l2h[g] : g_l3h[g];
    if (i < n) {
        float4 v = *reinterpret_cast<const float4*>(&s[i]);
        __half2 h0 = __floats2half2_rn(v.x, v.y);
        __half2 h1 = __floats2half2_rn(v.z, v.w);
        *reinterpret_cast<uint2*>(&d[i]) =
            make_uint2(*reinterpret_cast<unsigned*>(&h0), *reinterpret_cast<unsigned*>(&h1));
    }
}

// ---------------- edge / degree prep (both graphs batched: blockIdx.y = g) --
__global__ void init_kernel() {
    int i = blockIdx.x * blockDim.x + threadIdx.x;
    int g = blockIdx.y;
    if (i < N_NODES) { g_dinv[g][i] = 1.0f; g_hist[g][i] = 0; }
}

__global__ void edge_kernel(const float* __restrict__ d0, const float* __restrict__ d1,
                            const int* __restrict__ e0, const int* __restrict__ e1) {
    int e = blockIdx.x * blockDim.x + threadIdx.x;
    int g = blockIdx.y;
    const float* data = g ? d1 : d0;
    const int*   ei   = g ? e1 : e0;
    if (e < N_EDGES) {
        int r = ei[e];
        int c = ei[N_EDGES + e];
        float v = fmaxf(data[(size_t)r * N_NODES + c], 0.0f);
        g_w[g][e] = v;
        atomicAdd(&g_dinv[g][c], v);
        atomicAdd(&g_hist[g][c], 1);
    }
}

__global__ void scan_dinv_kernel() {
    __shared__ int s[1024];
    int g = blockIdx.x;
    int t = threadIdx.x;
    for (int i = t; i < N_NODES; i += 1024)
        g_dinv[g][i] = rsqrtf(g_dinv[g][i]);
    int base = t * 8;
    int loc[8];
    int sum = 0;
#pragma unroll
    for (int j = 0; j < 8; j++) {
        int i = base + j;
        int v = (i < N_NODES) ? g_hist[g][i] : 0;
        loc[j] = sum;
        sum += v;
    }
    s[t] = sum;
    __syncthreads();
    for (int d = 1; d < 1024; d <<= 1) {
        int v = (t >= d) ? s[t - d] : 0;
        __syncthreads();
        s[t] += v;
        __syncthreads();
    }
    int cbase = s[t] - sum;
#pragma unroll
    for (int j = 0; j < 8; j++) {
        int i = base + j;
        if (i < N_NODES) {
            int o = cbase + loc[j];
            g_offs[g][i] = o;
            g_fill[g][i] = o;
        }
    }
    if (t == 0) g_offs[g][N_NODES] = N_EDGES;
}

__global__ void scatter_coeff_kernel(const int* __restrict__ e0, const int* __restrict__ e1) {
    int e = blockIdx.x * blockDim.x + threadIdx.x;
    int g = blockIdx.y;
    const int* ei = g ? e1 : e0;
    if (e < N_EDGES) {
        int r = ei[e];
        int c = ei[N_EDGES + e];
        float cf = g_dinv[g][r] * g_w[g][e] * g_dinv[g][c];
        int p = atomicAdd(&g_fill[g][c], 1);
        g_crow[g][p]  = r;
        g_ccoef[g][p] = cf;
    }
}

// ---------------- GCN aggregation (fp16 gather, fp32 accum, fp16 out) --------
__global__ void aggregate_kernel(const float* __restrict__ bias0,
                                 const float* __restrict__ bias1) {
    int c = blockIdx.x;
    int g = blockIdx.y;
    const float* bias = g ? bias1 : bias0;
    const __half* __restrict__ th = g_th[g];
    __half* outh = g_hh[g];
    const int* __restrict__ crow = g_crow[g];
    const float* __restrict__ ccoef = g_ccoef[g];
    int f = threadIdx.x * 4;
    float dv = g_dinv[g][c];
    float sc = dv * dv;
    uint2 sraw = *reinterpret_cast<const uint2*>(&th[(size_t)c * F0 + f]);
    float2 s0 = __half22float2(*reinterpret_cast<__half2*>(&sraw.x));
    float2 s1 = __half22float2(*reinterpret_cast<__half2*>(&sraw.y));
    float4 acc = make_float4(s0.x * sc, s0.y * sc, s1.x * sc, s1.y * sc);
    int e0 = g_offs[g][c], e1 = g_offs[g][c + 1];
#pragma unroll 4
    for (int e = e0; e < e1; e++) {
        int   r  = crow[e];
        float cf = ccoef[e];
        uint2 raw = *reinterpret_cast<const uint2*>(&th[(size_t)r * F0 + f]);
        float2 u0 = __half22float2(*reinterpret_cast<__half2*>(&raw.x));
        float2 u1 = __half22float2(*reinterpret_cast<__half2*>(&raw.y));
        acc.x += cf * u0.x; acc.y += cf * u0.y;
        acc.z += cf * u1.x; acc.w += cf * u1.y;
    }
    float4 b = *reinterpret_cast<const float4*>(&bias[f]);
    acc.x = fmaxf(acc.x + b.x, 0.0f);
    acc.y = fmaxf(acc.y + b.y, 0.0f);
    acc.z = fmaxf(acc.z + b.z, 0.0f);
    acc.w = fmaxf(acc.w + b.w, 0.0f);
    __half2 h0 = __floats2half2_rn(acc.x, acc.y);
    __half2 h1 = __floats2half2_rn(acc.z, acc.w);
    *reinterpret_cast<uint2*>(&outh[(size_t)c * F0 + f]) =
        make_uint2(*reinterpret_cast<unsigned*>(&h0), *reinterpret_cast<unsigned*>(&h1));
}

// ---------------- FP16 tensor-core GEMM (BK=64, dynamic SMEM) ----------------
// 128x128x64 tile, 256 threads, 2-stage double buffer, cp.async + ldmatrix.
// C[Mn,Nn] = A[Mn,Kn] @ B  (B is [Kn,Nn] if !TRANSB else [Nn,Kn]); Kn % 64 == 0.
// OUTM: 0 = fp32 C, 1 = fp16 C.
// Dynamic smem: A0,A1 (18KB each), B0,B1 (17KB or 18KB each) = 72KB.
#define GEMM_SMEM_BYTES 73728

__device__ __forceinline__ void ldsm_x4(unsigned& r0, unsigned& r1,
                                        unsigned& r2, unsigned& r3, unsigned addr) {
    asm volatile("ldmatrix.sync.aligned.m8n8.x4.shared.b16 {%0,%1,%2,%3}, [%4];"
                 : "=r"(r0), "=r"(r1), "=r"(r2), "=r"(r3) : "r"(addr));
}
__device__ __forceinline__ void ldsm_x4_trans(unsigned& r0, unsigned& r1,
                                              unsigned& r2, unsigned& r3, unsigned addr) {
    asm volatile("ldmatrix.sync.aligned.m8n8.x4.trans.shared.b16 {%0,%1,%2,%3}, [%4];"
                 : "=r"(r0), "=r"(r1), "=r"(r2), "=r"(r3) : "r"(addr));
}
__device__ __forceinline__ void cpasync16(unsigned dst, const void* src) {
    asm volatile("cp.async.cg.shared.global [%0], [%1], 16;" :: "r"(dst), "l"(src));
}

template <bool TRANSB, bool BIAS, bool RELU, int OUTM>
__global__ __launch_bounds__(256, 2)
void fp16_gemm(const __half* __restrict__ A0, const __half* __restrict__ A1,
               const __half* __restrict__ B0, const __half* __restrict__ B1,
               const float* __restrict__ bias0, const float* __restrict__ bias1,
               void* __restrict__ C0v, void* __restrict__ C1v,
               int Mn, int Nn, int Kn) {
    constexpr int BM = 128, BN = 128, BK = 64;
    constexpr int LDA  = BK / 2 + 4;  // 36 words = 144B rows: 9r mod 8 -> conflict-free
    constexpr int LDB2 = BK / 2 + 4;  // TRANSB: same layout as A
    constexpr int LDBH = BN + 8;      // !TRANSB: [k][n] halves, 272B rows
    constexpr int ASZ = BM * LDA;                                // words (4608)
    constexpr int BSZ = TRANSB ? (BN * LDB2) : (BK * LDBH / 2);  // words
    extern __shared__ __align__(16) unsigned dsm[];

    const int gsel = blockIdx.z;
    const __half* A   = gsel ? A1 : A0;
    const __half* B   = gsel ? B1 : B0;
    const float* bias = gsel ? bias1 : bias0;
    void*        Cv   = gsel ? C1v : C0v;

    const int tid  = threadIdx.x;
    const int lane = tid & 31;
    const int wid  = tid >> 5;
    const int wm   = (wid & 1) * 64;
    const int wn   = (wid >> 1) * 32;
    const int q    = lane >> 2;
    const int r    = lane & 3;
    const int m0   = blockIdx.y * BM;
    const int n0   = blockIdx.x * BN;

    const int la_row  = ((lane >> 3) & 1) * 8 + (lane & 7);
    const int la_koff = ((lane >> 4) & 1) * 4;
    const int lbt_row = ((lane >> 4) & 1) * 8 + (lane & 7);
    const int lbt_koff= ((lane >> 3) & 1) * 4;
    const int lbn_k   = ((lane >> 3) & 1) * 8 + (lane & 7);
    const int lbn_n   = ((lane >> 4) & 1) * 8;

    const unsigned smem0   = (unsigned)__cvta_generic_to_shared(dsm);
    const unsigned as_base = smem0;
    const unsigned bs_base = smem0 + 2 * ASZ * 4;

    float c[4][4][4];
#pragma unroll
    for (int i = 0; i < 4; i++)
#pragma unroll
        for (int j = 0; j < 4; j++)
#pragma unroll
            for (int k = 0; k < 4; k++) c[i][j][k] = 0.0f;

    // A tile: 128 rows x 8 chunks(16B) = 1024 tasks, 4/thread
    auto prefetchA = [&](int st, int k0) {
        unsigned dstb = as_base + st * ASZ * 4;
#pragma unroll
        for (int i = 0; i < 4; i++) {
            int p = tid + i * 256;
            int row = p >> 3;
            int ch  = p & 7;
            int gr = m0 + row; if (gr > Mn - 1) gr = Mn - 1;
            cpasync16(dstb + (unsigned)(row * 144 + ch * 16),
                      A + (size_t)gr * Kn + k0 + ch * 8);
        }
    };
    auto prefetchB = [&](int st, int k0) {
        unsigned dstb = bs_base + st * BSZ * 4;
        if (!TRANSB) {
            // 64 k-rows x 16 chunks = 1024 tasks
#pragma unroll
            for (int i = 0; i < 4; i++) {
                int p  = tid + i * 256;
                int kp = p >> 4;
                int ch = p & 15;
                cpasync16(dstb + (unsigned)(kp * 272 + ch * 16),
                          B + (size_t)(k0 + kp) * Nn + n0 + ch * 8);
            }
        } else {
            // 128 n-rows x 8 chunks = 1024 tasks
#pragma unroll
            for (int i = 0; i < 4; i++) {
                int p = tid + i * 256;
                int row = p >> 3;
                int ch  = p & 7;
                int gn = n0 + row; if (gn > Nn - 1) gn = Nn - 1;
                cpasync16(dstb + (unsigned)(row * 144 + ch * 16),
                          B + (size_t)gn * Kn + k0 + ch * 8);
            }
        }
    };
    auto compute = [&](int st) {
        const unsigned a_st = as_base + st * ASZ * 4;
        const unsigned b_st = bs_base + st * BSZ * 4;
#pragma unroll
        for (int half = 0; half < 2; half++) {
            unsigned a[2][4][4], b[2][4][2];
#pragma unroll
            for (int hh = 0; hh < 2; hh++) {
                int ks = half * 16 + hh * 8;   // word offset within row
#pragma unroll
                for (int tm = 0; tm < 4; tm++) {
                    unsigned addr = a_st +
                        ((unsigned)((wm + tm * 16 + la_row) * LDA + ks + la_koff) << 2);
                    ldsm_x4(a[hh][tm][0], a[hh][tm][1], a[hh][tm][2], a[hh][tm][3], addr);
                }
                if (!TRANSB) {
#pragma unroll
                    for (int tp = 0; tp < 2; tp++) {
                        unsigned addr = b_st +
                            ((unsigned)((2 * ks + lbn_k) * LDBH + wn + tp * 16 + lbn_n) << 1);
                        ldsm_x4_trans(b[hh][2 * tp][0], b[hh][2 * tp][1],
                                      b[hh][2 * tp + 1][0], b[hh][2 * tp + 1][1], addr);
                    }
                } else {
#pragma unroll
                    for (int tp = 0; tp < 2; tp++) {
                        unsigned addr = b_st +
                            ((unsigned)((wn + tp * 16 + lbt_row) * LDB2 + ks + lbt_koff) << 2);
                        ldsm_x4(b[hh][2 * tp][0], b[hh][2 * tp][1],
                                b[hh][2 * tp + 1][0], b[hh][2 * tp + 1][1], addr);
                    }
                }
            }
#pragma unroll
            for (int hh = 0; hh < 2; hh++)
#pragma unroll
                for (int tm = 0; tm < 4; tm++)
#pragma unroll
                    for (int tn = 0; tn < 4; tn++) {
                        asm volatile(
                            "mma.sync.aligned.m16n8k16.row.col.f32.f16.f16.f32 "
                            "{%0,%1,%2,%3}, {%4,%5,%6,%7}, {%8,%9}, {%0,%1,%2,%3};"
                            : "+f"(c[tm][tn][0]), "+f"(c[tm][tn][1]),
                              "+f"(c[tm][tn][2]), "+f"(c[tm][tn][3])
                            : "r"(a[hh][tm][0]), "r"(a[hh][tm][1]),
                              "r"(a[hh][tm][2]), "r"(a[hh][tm][3]),
                              "r"(b[hh][tn][0]), "r"(b[hh][tn][1]));
                    }
        }
    };

    prefetchA(0, 0);
    prefetchB(0, 0);
    asm volatile("cp.async.commit_group;");

    int s = 0;
    for (int k0 = 0; k0 < Kn; k0 += BK, s ^= 1) {
        asm volatile("cp.async.wait_group 0;");
        __syncthreads();
        bool next = (k0 + BK) < Kn;
        if (next) {
            prefetchA(s ^ 1, k0 + BK);
            prefetchB(s ^ 1, k0 + BK);
            asm volatile("cp.async.commit_group;");
        }
        compute(s);
    }

    // epilogue
#pragma unroll
    for (int tm = 0; tm < 4; tm++) {
        int row = m0 + wm + tm * 16 + q;
#pragma unroll
        for (int tn = 0; tn < 4; tn++) {
            int col = n0 + wn + tn * 8 + 2 * r;
            if (col >= Nn) continue;
            float v0 = c[tm][tn][0], v1 = c[tm][tn][1];
            float v2 = c[tm][tn][2], v3 = c[tm][tn][3];
            if (BIAS) {
                float bb0 = bias[col], bb1 = bias[col + 1];
                v0 += bb0; v1 += bb1; v2 += bb0; v3 += bb1;
            }
            if (RELU) {
                v0 = fmaxf(v0, 0.f); v1 = fmaxf(v1, 0.f);
                v2 = fmaxf(v2, 0.f); v3 = fmaxf(v3, 0.f);
            }
            if (OUTM == 0) {
                float* Cf = reinterpret_cast<float*>(Cv);
                if (row < Mn)
                    *reinterpret_cast<float2*>(&Cf[(size_t)row * Nn + col]) = make_float2(v0, v1);
                if (row + 8 < Mn)
                    *reinterpret_cast<float2*>(&Cf[(size_t)(row + 8) * Nn + col]) = make_float2(v2, v3);
            } else {
                __half* Ch = reinterpret_cast<__half*>(Cv);
                if (row < Mn) {
                    __half2 p = __floats2half2_rn(v0, v1);
                    *reinterpret_cast<unsigned*>(&Ch[(size_t)row * Nn + col]) =
                        *reinterpret_cast<unsigned*>(&p);
                }
                if (row + 8 < Mn) {
                    __half2 p = __floats2half2_rn(v2, v3);
                    *reinterpret_cast<unsigned*>(&Ch[(size_t)(row + 8) * Nn + col]) =
                        *reinterpret_cast<unsigned*>(&p);
                }
            }
        }
    }
}

// ---------------- host-side orchestration -----------------------------------
extern "C" void kernel_launch(void* const* d_in, const int* in_sizes, int n_in,
                              void* d_out, int out_size) {
    const float* x_in[2]  = { (const float*)d_in[0], (const float*)d_in[1] };
    const float* dmat[2]  = { (const float*)d_in[2], (const float*)d_in[3] };
    const int*   ei[2]    = { (const int*)d_in[4],   (const int*)d_in[5]   };
    const float* W1[2]    = { (const float*)d_in[6],  (const float*)d_in[10] };
    const float* b1[2]    = { (const float*)d_in[7],  (const float*)d_in[11] };
    const float* W2[2]    = { (const float*)d_in[8],  (const float*)d_in[12] };
    const float* b2[2]    = { (const float*)d_in[9],  (const float*)d_in[13] };
    const float* L1w[2]   = { (const float*)d_in[14], (const float*)d_in[20] };
    const float* L1b[2]   = { (const float*)d_in[15], (const float*)d_in[21] };
    const float* L2w[2]   = { (const float*)d_in[16], (const float*)d_in[22] };
    const float* L2b[2]   = { (const float*)d_in[17], (const float*)d_in[23] };
    const float* L3w[2]   = { (const float*)d_in[18], (const float*)d_in[24] };
    const float* L3b[2]   = { (const float*)d_in[19], (const float*)d_in[25] };
    float* out = (float*)d_out;

    __half *p_xh, *p_th, *p_hh, *p_w1h, *p_w2h, *p_l1h, *p_l2h, *p_l3h;
    __half *p_m1h, *p_m2h, *p_m3h;
    cudaGetSymbolAddress((void**)&p_xh,  g_xh);
    cudaGetSymbolAddress((void**)&p_th,  g_th);
    cudaGetSymbolAddress((void**)&p_hh,  g_hh);
    cudaGetSymbolAddress((void**)&p_w1h, g_w1h);
    cudaGetSymbolAddress((void**)&p_w2h, g_w2h);
    cudaGetSymbolAddress((void**)&p_l1h, g_l1h);
    cudaGetSymbolAddress((void**)&p_l2h, g_l2h);
    cudaGetSymbolAddress((void**)&p_l3h, g_l3h);
    cudaGetSymbolAddress((void**)&p_m1h, g_m1h);
    cudaGetSymbolAddress((void**)&p_m2h, g_m2h);
    cudaGetSymbolAddress((void**)&p_m3h, g_m3h);

    __half* xh[2]  = { p_xh,  p_xh  + (size_t)N_NODES * F0 };
    __half* th[2]  = { p_th,  p_th  + (size_t)N_NODES * F0 };
    __half* hh[2]  = { p_hh,  p_hh  + (size_t)N_NODES * F0 };
    __half* w1h[2] = { p_w1h, p_w1h + (size_t)F0 * F0 };
    __half* w2h[2] = { p_w2h, p_w2h + (size_t)F0 * F0 };
    __half* l1h[2] = { p_l1h, p_l1h + (size_t)F0 * 256 };
    __half* l2h[2] = { p_l2h, p_l2h + (size_t)256 * 128 };
    __half* l3h[2] = { p_l3h, p_l3h + (size_t)(128 * 64 + 64) };
    __half* m1h[2] = { p_m1h, p_m1h + (size_t)N_NODES * 256 };
    __half* m2h[2] = { p_m2h, p_m2h + (size_t)N_NODES * 128 };
    __half* m3h[2] = { p_m3h, p_m3h + (size_t)N_NODES * 64 };

    // opt-in to 72KB dynamic SMEM (idempotent)
    cudaFuncSetAttribute(fp16_gemm<false, false, false, 1>,
                         cudaFuncAttributeMaxDynamicSharedMemorySize, GEMM_SMEM_BYTES);
    cudaFuncSetAttribute(fp16_gemm<false, true, true, 1>,
                         cudaFuncAttributeMaxDynamicSharedMemorySize, GEMM_SMEM_BYTES);
    cudaFuncSetAttribute(fp16_gemm<true, false, false, 0>,
                         cudaFuncAttributeMaxDynamicSharedMemorySize, GEMM_SMEM_BYTES);

    const int TB = 256;
    const dim3 gN((N_NODES + TB - 1) / TB, 2);
    const dim3 gE((N_EDGES + TB - 1) / TB, 2);
    const int MB = (N_NODES + 127) / 128;   // 63

    // 1-3: conversions + init (GEMM1 deps first so ncu slot 4 = fp16_gemm)
    conv_x_kernel<<<dim3((N_NODES * F0 / 4 + TB - 1) / TB, 2), TB>>>(x_in[0], x_in[1]);
    conv_w_kernel<<<dim3((F0 * F0 / 4 + TB - 1) / TB, 2, 5), TB>>>(
        W1[0], W1[1], W2[0], W2[1], L1w[0], L1w[1], L2w[0], L2w[1], L3w[0], L3w[1]);
    init_kernel<<<gN, TB>>>();

    // 4 (ncu capture slot): GCN layer-1 GEMM  th = fp16(x @ W1)
    fp16_gemm<false, false, false, 1><<<dim3(F0 / 128, MB, 2), 256, GEMM_SMEM_BYTES>>>(
        xh[0], xh[1], w1h[0], w1h[1], nullptr, nullptr, th[0], th[1],
        N_NODES, F0, F0);

    // finish edge prep
    edge_kernel<<<gE, TB>>>(dmat[0], dmat[1], ei[0], ei[1]);
    scan_dinv_kernel<<<2, 1024>>>();
    scatter_coeff_kernel<<<gE, TB>>>(ei[0], ei[1]);

    // agg1: hh = fp16(relu(agg(th) + b1))
    aggregate_kernel<<<dim3(N_NODES, 2), 128>>>(b1[0], b1[1]);

    // GCN layer 2
    fp16_gemm<false, false, false, 1><<<dim3(F0 / 128, MB, 2), 256, GEMM_SMEM_BYTES>>>(
        hh[0], hh[1], w2h[0], w2h[1], nullptr, nullptr, th[0], th[1],
        N_NODES, F0, F0);
    aggregate_kernel<<<dim3(N_NODES, 2), 128>>>(b2[0], b2[1]);

    // MLP (all fp16 tensor-core): 512->256->128->64
    fp16_gemm<false, true, true, 1><<<dim3(2, MB, 2), 256, GEMM_SMEM_BYTES>>>(
        hh[0], hh[1], l1h[0], l1h[1], L1b[0], L1b[1], m1h[0], m1h[1],
        N_NODES, 256, F0);
    fp16_gemm<false, true, true, 1><<<dim3(1, MB, 2), 256, GEMM_SMEM_BYTES>>>(
        m1h[0], m1h[1], l2h[0], l2h[1], L2b[0], L2b[1], m2h[0], m2h[1],
        N_NODES, 128, 256);
    fp16_gemm<false, true, true, 1><<<dim3(1, MB, 2), 256, GEMM_SMEM_BYTES>>>(
        m2h[0], m2h[1], l3h[0], l3h[1], L3b[0], L3b[1], m3h[0], m3h[1],
        N_NODES, 64, 128);

    // final (TRANSB): out = x64_m @ y64_d^T  [8000 x 8000]
    fp16_gemm<true, false, false, 0><<<dim3(MB, MB, 1), 256, GEMM_SMEM_BYTES>>>(
        m3h[0], m3h[0], m3h[1], m3h[1], nullptr, nullptr, out, out,
        N_NODES, N_NODES, 64);
}